// round 1
// baseline (speedup 1.0000x reference)
#include <cuda_runtime.h>
#include <math.h>

#define T_STEPS 128
#define NB      256
#define E_DIM   512
#define A_DIM   8
#define H_DIM   512
#define G3      1536        // 3*H
#define TN      (T_STEPS * NB)   // 32768
#define K_IN    (E_DIM + A_DIM)  // 520

// ---- scratch (device globals; no dynamic allocation allowed) ----
__device__ float g_GI[(size_t)TN * G3];   // precomputed input-side gates for gru (192 MiB)
__device__ float g_MA[TN * A_DIM];        // masked prev action
__device__ float g_GH[NB * 2 * G3];       // per-step hidden-side gates, both GRUs (3 MiB)

__device__ __forceinline__ float sigmoidf_(float x) { return 1.0f / (1.0f + expf(-x)); }

// ---------------------------------------------------------------------------
// Prep: ma[t,n,a] = prev_action_one_hot[t,n,a] * masks[t*N+n]
// ---------------------------------------------------------------------------
__global__ void ma_kernel(const float* __restrict__ pa, const float* __restrict__ masks) {
    int i = blockIdx.x * blockDim.x + threadIdx.x;
    if (i < TN * A_DIM) g_MA[i] = pa[i] * masks[i >> 3];
}

// ---------------------------------------------------------------------------
// Big input GEMM: GI[m, j] = sum_k X2[m,k] * w_ih[j,k] + b_ih[j]
//   X2 = concat(x (32768x512), MA (32768x8)) -> K = 520
// 64x64 tile, BK=16, 128 threads, 8x4 register tile per thread.
// grid: (1536/64=24, 32768/64=512)
// ---------------------------------------------------------------------------
__global__ void __launch_bounds__(128)
gemm_input_kernel(const float* __restrict__ x, const float* __restrict__ w_ih,
                  const float* __restrict__ b_ih) {
    __shared__ float As[16][65];
    __shared__ float Bs[16][65];
    const int j0  = blockIdx.x * 64;
    const int m0  = blockIdx.y * 64;
    const int tid = threadIdx.x;
    const int tx  = tid & 15;        // 16 col-threads
    const int ty  = tid >> 4;        // 8 row-threads
    const int lr  = tid >> 1;        // 0..63
    const int lk  = (tid & 1) * 8;   // 0 or 8

    float acc[8][4];
#pragma unroll
    for (int i = 0; i < 8; i++)
#pragma unroll
        for (int c = 0; c < 4; c++) acc[i][c] = 0.0f;

    const int m = m0 + lr;
    const int j = j0 + lr;

    for (int k0 = 0; k0 < K_IN; k0 += 16) {
#pragma unroll
        for (int u = 0; u < 8; u++) {
            int k = k0 + lk + u;
            float v = 0.0f;
            if (k < E_DIM)      v = x[(size_t)m * E_DIM + k];
            else if (k < K_IN)  v = g_MA[m * A_DIM + (k - E_DIM)];
            As[lk + u][lr] = v;
        }
#pragma unroll
        for (int u = 0; u < 8; u++) {
            int k = k0 + lk + u;
            float v = (k < K_IN) ? w_ih[(size_t)j * K_IN + k] : 0.0f;
            Bs[lk + u][lr] = v;
        }
        __syncthreads();
#pragma unroll
        for (int kk = 0; kk < 16; kk++) {
            float a[8], b[4];
#pragma unroll
            for (int i = 0; i < 8; i++) a[i] = As[kk][ty * 8 + i];
#pragma unroll
            for (int c = 0; c < 4; c++) b[c] = Bs[kk][tx * 4 + c];
#pragma unroll
            for (int i = 0; i < 8; i++)
#pragma unroll
                for (int c = 0; c < 4; c++) acc[i][c] += a[i] * b[c];
        }
        __syncthreads();
    }

#pragma unroll
    for (int i = 0; i < 8; i++) {
        int row = m0 + ty * 8 + i;
#pragma unroll
        for (int c = 0; c < 4; c++) {
            int col = j0 + tx * 4 + c;
            g_GI[(size_t)row * G3 + col] = acc[i][c] + b_ih[col];
        }
    }
}

// ---------------------------------------------------------------------------
// Per-step hidden GEMM for BOTH GRUs into g_GH (256 x 3072):
//   cols [0,1536):    GH  = (hx_prev * m)                  @ w_hh^T
//   cols [1536,3072): GHp = (hy_prev * m + g_t * (1-m))    @ w_hh_p^T
// grid: (48, 4); blockIdx.x < 24 -> gru, else gru_p
// ---------------------------------------------------------------------------
__global__ void __launch_bounds__(128)
gemm_step_kernel(const float* __restrict__ hx_prev, const float* __restrict__ hy_prev,
                 const float* __restrict__ masks_t, const float* __restrict__ g_t,
                 const float* __restrict__ w_hh, const float* __restrict__ w_hh_p) {
    __shared__ float As[16][65];
    __shared__ float Bs[16][65];
    const bool is_p = (blockIdx.x >= 24);
    const int j0 = (blockIdx.x - (is_p ? 24 : 0)) * 64;
    const int m0 = blockIdx.y * 64;
    const float* __restrict__ W = is_p ? w_hh_p : w_hh;

    const int tid = threadIdx.x;
    const int tx  = tid & 15;
    const int ty  = tid >> 4;
    const int lr  = tid >> 1;
    const int lk  = (tid & 1) * 8;

    float acc[8][4];
#pragma unroll
    for (int i = 0; i < 8; i++)
#pragma unroll
        for (int c = 0; c < 4; c++) acc[i][c] = 0.0f;

    const int m  = m0 + lr;
    const int j  = j0 + lr;
    const float mm  = masks_t[m];
    const float omm = 1.0f - mm;
    const float* __restrict__ hxr = is_p ? (hy_prev + (size_t)m * H_DIM)
                                         : (hx_prev + (size_t)m * H_DIM);
    const float* __restrict__ gtr = g_t + (size_t)m * H_DIM;

    for (int k0 = 0; k0 < H_DIM; k0 += 16) {
#pragma unroll
        for (int u = 0; u < 8; u++) {
            int k = k0 + lk + u;
            float v = hxr[k] * mm;
            if (is_p) v += gtr[k] * omm;
            As[lk + u][lr] = v;
        }
#pragma unroll
        for (int u = 0; u < 8; u++) {
            int k = k0 + lk + u;
            Bs[lk + u][lr] = W[(size_t)j * H_DIM + k];
        }
        __syncthreads();
#pragma unroll
        for (int kk = 0; kk < 16; kk++) {
            float a[8], b[4];
#pragma unroll
            for (int i = 0; i < 8; i++) a[i] = As[kk][ty * 8 + i];
#pragma unroll
            for (int c = 0; c < 4; c++) b[c] = Bs[kk][tx * 4 + c];
#pragma unroll
            for (int i = 0; i < 8; i++)
#pragma unroll
                for (int c = 0; c < 4; c++) acc[i][c] += a[i] * b[c];
        }
        __syncthreads();
    }

    const int cbase = (is_p ? G3 : 0) + j0;
#pragma unroll
    for (int i = 0; i < 8; i++) {
        int row = m0 + ty * 8 + i;
#pragma unroll
        for (int c = 0; c < 4; c++) {
            g_GH[row * (2 * G3) + cbase + tx * 4 + c] = acc[i][c];
        }
    }
}

// ---------------------------------------------------------------------------
// Fused elementwise gate math for both GRUs. gip (K=8) computed inline.
// grid: (512, 256 threads) => 131072 threads = N*H
// ---------------------------------------------------------------------------
__global__ void __launch_bounds__(256)
gate_kernel(int t,
            const float* __restrict__ masks_t,
            const float* __restrict__ hx_prev, const float* __restrict__ hy_prev,
            const float* __restrict__ g_t,
            const float* __restrict__ w_ih_p, const float* __restrict__ b_ih_p,
            const float* __restrict__ b_hh,   const float* __restrict__ b_hh_p,
            float* __restrict__ hx_out, float* __restrict__ hy_out) {
    int i = blockIdx.x * blockDim.x + threadIdx.x;   // 0..131071
    int n = i >> 9;          // batch row
    int j = i & 511;         // hidden unit
    const float m = masks_t[n];

    const float* __restrict__ gi = g_GI + ((size_t)t * NB + n) * G3;
    const float* __restrict__ gh = g_GH + n * (2 * G3);

    // --- gru (obs+action) ---
    {
        float hr = gh[j]               + b_hh[j];
        float hz = gh[j + H_DIM]       + b_hh[j + H_DIM];
        float hn = gh[j + 2 * H_DIM]   + b_hh[j + 2 * H_DIM];
        float r  = sigmoidf_(gi[j]             + hr);
        float z  = sigmoidf_(gi[j + H_DIM]     + hz);
        float nn = tanhf   (gi[j + 2 * H_DIM] + r * hn);
        float hmask = hx_prev[(size_t)n * H_DIM + j] * m;
        hx_out[(size_t)n * H_DIM + j] = (1.0f - z) * nn + z * hmask;
    }

    // --- gru_p (action only): gip computed inline (K=8) ---
    {
        const float* __restrict__ ghp = gh + G3;
        const float* __restrict__ man = g_MA + ((size_t)t * NB + n) * A_DIM;
        float ir  = b_ih_p[j];
        float iz  = b_ih_p[j + H_DIM];
        float in_ = b_ih_p[j + 2 * H_DIM];
#pragma unroll
        for (int a = 0; a < A_DIM; a++) {
            float mv = man[a];
            ir  += mv * w_ih_p[(j)             * A_DIM + a];
            iz  += mv * w_ih_p[(j + H_DIM)     * A_DIM + a];
            in_ += mv * w_ih_p[(j + 2 * H_DIM) * A_DIM + a];
        }
        float hr = ghp[j]             + b_hh_p[j];
        float hz = ghp[j + H_DIM]     + b_hh_p[j + H_DIM];
        float hn = ghp[j + 2 * H_DIM] + b_hh_p[j + 2 * H_DIM];
        float r  = sigmoidf_(ir  + hr);
        float z  = sigmoidf_(iz  + hz);
        float nn = tanhf   (in_ + r * hn);
        float hin = hy_prev[(size_t)n * H_DIM + j] * m
                  + g_t[(size_t)n * H_DIM + j] * (1.0f - m);
        hy_out[(size_t)n * H_DIM + j] = (1.0f - z) * nn + z * hin;
    }
}

// ---------------------------------------------------------------------------
// Launch
// ---------------------------------------------------------------------------
extern "C" void kernel_launch(void* const* d_in, const int* in_sizes, int n_in,
                              void* d_out, int out_size) {
    const float* x        = (const float*)d_in[0];
    const float* hxs      = (const float*)d_in[1];
    const float* hys      = (const float*)d_in[2];
    const float* gru_init = (const float*)d_in[3];
    const float* masks    = (const float*)d_in[4];
    const float* pa       = (const float*)d_in[5];
    const float* w_ih     = (const float*)d_in[6];
    const float* w_hh     = (const float*)d_in[7];
    const float* b_ih     = (const float*)d_in[8];
    const float* b_hh     = (const float*)d_in[9];
    const float* w_ih_p   = (const float*)d_in[10];
    const float* w_hh_p   = (const float*)d_in[11];
    const float* b_ih_p   = (const float*)d_in[12];
    const float* b_hh_p   = (const float*)d_in[13];

    float* out      = (float*)d_out;
    float* outs     = out;                                   // (TN, H)
    float* hxs_out  = outs + (size_t)TN * H_DIM;             // (N, H)
    float* outs_p   = hxs_out + (size_t)NB * H_DIM;          // (TN, H)
    float* hys_out  = outs_p + (size_t)TN * H_DIM;           // (N, H)

    // 1) masked prev-action
    ma_kernel<<<(TN * A_DIM + 255) / 256, 256>>>(pa, masks);

    // 2) big input GEMM for gru: GI = concat(x, ma) @ w_ih^T + b_ih
    gemm_input_kernel<<<dim3(G3 / 64, TN / 64), 128>>>(x, w_ih, b_ih);

    // 3) sequential scan
    const float* hx_prev = hxs;
    const float* hy_prev = hys;
    for (int t = 0; t < T_STEPS; t++) {
        const float* masks_t = masks + (size_t)t * NB;
        const float* g_t     = gru_init + (size_t)t * NB * H_DIM;
        float* hx_out = outs   + (size_t)t * NB * H_DIM;
        float* hy_out = outs_p + (size_t)t * NB * H_DIM;

        gemm_step_kernel<<<dim3(48, 4), 128>>>(hx_prev, hy_prev, masks_t, g_t,
                                               w_hh, w_hh_p);
        gate_kernel<<<512, 256>>>(t, masks_t, hx_prev, hy_prev, g_t,
                                  w_ih_p, b_ih_p, b_hh, b_hh_p,
                                  hx_out, hy_out);
        hx_prev = hx_out;
        hy_prev = hy_out;
    }

    // 4) final hidden states = last timestep outputs
    cudaMemcpyAsync(hxs_out, outs   + (size_t)(T_STEPS - 1) * NB * H_DIM,
                    (size_t)NB * H_DIM * sizeof(float), cudaMemcpyDeviceToDevice);
    cudaMemcpyAsync(hys_out, outs_p + (size_t)(T_STEPS - 1) * NB * H_DIM,
                    (size_t)NB * H_DIM * sizeof(float), cudaMemcpyDeviceToDevice);
}

// round 6
// speedup vs baseline: 1.6435x; 1.6435x over previous
#include <cuda_runtime.h>
#include <math.h>

#define T_STEPS 128
#define NB      256
#define E_DIM   512
#define A_DIM   8
#define H_DIM   512
#define G3      1536
#define TN      (T_STEPS * NB)
#define K_IN    (E_DIM + A_DIM)

// ---- scratch (device globals; no dynamic allocation allowed) ----
__device__ float g_GI[(size_t)TN * G3];   // input-side gates for gru (192 MiB)
__device__ float g_MA[TN * A_DIM];        // masked prev action

__device__ __forceinline__ float sigmoidf_(float x) { return 1.0f / (1.0f + expf(-x)); }

// ---------------------------------------------------------------------------
// Prep: ma[t,n,a] = prev_action_one_hot[t,n,a] * masks[t*N+n]   (round-1, proven)
// ---------------------------------------------------------------------------
__global__ void ma_kernel(const float* __restrict__ pa, const float* __restrict__ masks) {
    int i = blockIdx.x * blockDim.x + threadIdx.x;
    if (i < TN * A_DIM) g_MA[i] = pa[i] * masks[i >> 3];
}

// ---------------------------------------------------------------------------
// Big input GEMM (round-1, proven): GI[m, j] = sum_k X2[m,k]*w_ih[j,k] + b_ih[j]
//   X2 = concat(x (32768x512), MA (32768x8)) -> K = 520
// 64x64 tile, BK=16, 128 threads, 8x4 register tile per thread.
// grid: (1536/64=24, 32768/64=512)
// ---------------------------------------------------------------------------
__global__ void __launch_bounds__(128)
gemm_input_kernel(const float* __restrict__ x, const float* __restrict__ w_ih,
                  const float* __restrict__ b_ih) {
    __shared__ float As[16][65];
    __shared__ float Bs[16][65];
    const int j0  = blockIdx.x * 64;
    const int m0  = blockIdx.y * 64;
    const int tid = threadIdx.x;
    const int tx  = tid & 15;        // 16 col-threads
    const int ty  = tid >> 4;        // 8 row-threads
    const int lr  = tid >> 1;        // 0..63
    const int lk  = (tid & 1) * 8;   // 0 or 8

    float acc[8][4];
#pragma unroll
    for (int i = 0; i < 8; i++)
#pragma unroll
        for (int c = 0; c < 4; c++) acc[i][c] = 0.0f;

    const int m = m0 + lr;
    const int j = j0 + lr;

    for (int k0 = 0; k0 < K_IN; k0 += 16) {
#pragma unroll
        for (int u = 0; u < 8; u++) {
            int k = k0 + lk + u;
            float v = 0.0f;
            if (k < E_DIM)      v = x[(size_t)m * E_DIM + k];
            else if (k < K_IN)  v = g_MA[m * A_DIM + (k - E_DIM)];
            As[lk + u][lr] = v;
        }
#pragma unroll
        for (int u = 0; u < 8; u++) {
            int k = k0 + lk + u;
            float v = (k < K_IN) ? w_ih[(size_t)j * K_IN + k] : 0.0f;
            Bs[lk + u][lr] = v;
        }
        __syncthreads();
#pragma unroll
        for (int kk = 0; kk < 16; kk++) {
            float a[8], b[4];
#pragma unroll
            for (int i = 0; i < 8; i++) a[i] = As[kk][ty * 8 + i];
#pragma unroll
            for (int c = 0; c < 4; c++) b[c] = Bs[kk][tx * 4 + c];
#pragma unroll
            for (int i = 0; i < 8; i++)
#pragma unroll
                for (int c = 0; c < 4; c++) acc[i][c] += a[i] * b[c];
        }
        __syncthreads();
    }

#pragma unroll
    for (int i = 0; i < 8; i++) {
        int row = m0 + ty * 8 + i;
#pragma unroll
        for (int c = 0; c < 4; c++) {
            int col = j0 + tx * 4 + c;
            g_GI[(size_t)row * G3 + col] = acc[i][c] + b_ih[col];
        }
    }
}

// ---------------------------------------------------------------------------
// Fused step kernel (fp32 SIMT): hidden GEMM + gate epilogue, both GRUs.
// 128 CTAs x 256 threads. cta -> (gru, 16-col j-slice, 128-row half).
// Each CTA computes C[128 rows x 48 gate-cols] over K=512, then the GRU gate
// math (gru_p input gates K=8 computed inline from w_ih_p, like round 1).
// Staging: A transposed [k][row] for LDS.128 over rows; W transposed [k][s].
// Register-prefetch double buffering (1 LDG batch in flight during compute).
// ---------------------------------------------------------------------------
#define AP 136   // A staging pitch (rows dim)
#define WSP 56   // W staging / C pitch

__global__ void __launch_bounds__(256)
step_kernel(int t,
            const float* __restrict__ hx_prev, const float* __restrict__ hy_prev,
            const float* __restrict__ masks_t, const float* __restrict__ g_t,
            const float* __restrict__ w_hh, const float* __restrict__ w_hh_p,
            const float* __restrict__ b_hh, const float* __restrict__ b_hh_p,
            const float* __restrict__ w_ih_p, const float* __restrict__ b_ih_p,
            float* __restrict__ hx_out, float* __restrict__ hy_out) {
    __shared__ __align__(16) float pool[128 * WSP];   // staging (As|Ws) then C
    __shared__ float wp[48 * 8];
    __shared__ float bgs[48];
    __shared__ float bip[48];

    float* As = pool;                 // [16][AP]   (16*136 = 2176 floats)
    float* Ws = pool + 16 * AP;       // [16][WSP]  (16*56  = 896 floats)

    const int cta = blockIdx.x;
    const bool isp = (cta >= 64);
    const int q = cta & 63;
    const int j0 = (q >> 1) * 16;
    const int mbase = (q & 1) * 128;

    const float* __restrict__ Wg = isp ? w_hh_p : w_hh;
    const float* __restrict__ bh = isp ? b_hh_p : b_hh;
    const float* __restrict__ hp = isp ? hy_prev : hx_prev;
    float* __restrict__ hout     = isp ? hy_out  : hx_out;

    const int tid = threadIdx.x;
    // staging roles
    const int lr = tid >> 1;            // A row 0..127
    const int kh = (tid & 1) * 8;       // A k-half
    const int sW = tid >> 2;            // W s-row (valid tid<192)
    const int segW = (tid & 3) * 4;     // W k-segment
    // compute roles
    const int rg = tid >> 3;            // 0..31 -> rows rg*4..+3
    const int cg = tid & 7;             // 0..7  -> cols cg*6..+5

    const int grow = mbase + lr;
    const float mr = masks_t[grow];
    const float omr = 1.0f - mr;
    const float* __restrict__ hrow = hp  + (size_t)grow * H_DIM;
    const float* __restrict__ grw  = g_t + (size_t)grow * H_DIM;

    // stage biases + gru_p input weights (straight-line, pre-first-sync)
    if (tid < 48) {
        const int gidx = (tid >> 4) * H_DIM + j0 + (tid & 15);
        bgs[tid] = bh[gidx];
        bip[tid] = b_ih_p[gidx];
    }
    if (tid < 96) {
        const int s = tid >> 1, hf = (tid & 1) * 4;
        const int gidx = (s >> 4) * H_DIM + j0 + (s & 15);
        *(float4*)&wp[s * 8 + hf] = *(const float4*)&w_ih_p[(size_t)gidx * A_DIM + hf];
    }

    const int wrow = (sW >> 4) * H_DIM + j0 + (sW & 15);   // W global row for this thread
    const float* __restrict__ Wrow = Wg + (size_t)wrow * H_DIM;

    float acc[4][6];
#pragma unroll
    for (int i = 0; i < 4; i++)
#pragma unroll
        for (int c = 0; c < 6; c++) acc[i][c] = 0.0f;

    // prefetch chunk 0
    float av[8];
    float4 wv;
    {
        float4 h0 = *(const float4*)(hrow + kh);
        float4 h1 = *(const float4*)(hrow + kh + 4);
        av[0]=h0.x; av[1]=h0.y; av[2]=h0.z; av[3]=h0.w;
        av[4]=h1.x; av[5]=h1.y; av[6]=h1.z; av[7]=h1.w;
        if (isp) {
            float4 g0 = *(const float4*)(grw + kh);
            float4 g1 = *(const float4*)(grw + kh + 4);
            float gv[8] = {g0.x,g0.y,g0.z,g0.w,g1.x,g1.y,g1.z,g1.w};
#pragma unroll
            for (int u = 0; u < 8; u++) av[u] = av[u] * mr + gv[u] * omr;
        } else {
#pragma unroll
            for (int u = 0; u < 8; u++) av[u] = av[u] * mr;
        }
        if (tid < 192) wv = *(const float4*)(Wrow + segW);
    }

    for (int ch = 0; ch < 32; ch++) {
        // store staged regs to smem (A transposed [k][row], W transposed [k][s])
#pragma unroll
        for (int u = 0; u < 8; u++) As[(kh + u) * AP + lr] = av[u];
        if (tid < 192) {
            Ws[(segW + 0) * WSP + sW] = wv.x;
            Ws[(segW + 1) * WSP + sW] = wv.y;
            Ws[(segW + 2) * WSP + sW] = wv.z;
            Ws[(segW + 3) * WSP + sW] = wv.w;
        }
        __syncthreads();

        // prefetch next chunk while computing this one
        if (ch < 31) {
            const int kb = (ch + 1) * 16 + kh;
            float4 h0 = *(const float4*)(hrow + kb);
            float4 h1 = *(const float4*)(hrow + kb + 4);
            av[0]=h0.x; av[1]=h0.y; av[2]=h0.z; av[3]=h0.w;
            av[4]=h1.x; av[5]=h1.y; av[6]=h1.z; av[7]=h1.w;
            if (isp) {
                float4 g0 = *(const float4*)(grw + kb);
                float4 g1 = *(const float4*)(grw + kb + 4);
                float gv[8] = {g0.x,g0.y,g0.z,g0.w,g1.x,g1.y,g1.z,g1.w};
#pragma unroll
                for (int u = 0; u < 8; u++) av[u] = av[u] * mr + gv[u] * omr;
            } else {
#pragma unroll
                for (int u = 0; u < 8; u++) av[u] = av[u] * mr;
            }
            if (tid < 192) wv = *(const float4*)(Wrow + (ch + 1) * 16 + segW);
        }

        // compute 16 k
#pragma unroll
        for (int k = 0; k < 16; k++) {
            float4 a4 = *(const float4*)&As[k * AP + rg * 4];
            const float* wk = &Ws[k * WSP + cg * 6];
            float w0 = wk[0], w1 = wk[1], w2 = wk[2],
                  w3 = wk[3], w4 = wk[4], w5 = wk[5];
            float a[4] = {a4.x, a4.y, a4.z, a4.w};
#pragma unroll
            for (int i = 0; i < 4; i++) {
                acc[i][0] += a[i] * w0;
                acc[i][1] += a[i] * w1;
                acc[i][2] += a[i] * w2;
                acc[i][3] += a[i] * w3;
                acc[i][4] += a[i] * w4;
                acc[i][5] += a[i] * w5;
            }
        }
        __syncthreads();
    }

    // ---- write C to smem (overlays staging; all staging reads complete) ----
#pragma unroll
    for (int i = 0; i < 4; i++)
#pragma unroll
        for (int c = 0; c < 6; c++)
            pool[(rg * 4 + i) * WSP + cg * 6 + c] = acc[i][c];
    __syncthreads();

    // ---- fused gate epilogue: thread -> row lr, 8 cols starting at kh ----
    const float* __restrict__ gi = g_GI + ((size_t)t * NB + grow) * G3 + j0;
    float ma8[8];
    if (isp) {
        float4 m0 = *(const float4*)&g_MA[((size_t)t * NB + grow) * A_DIM];
        float4 m1 = *(const float4*)&g_MA[((size_t)t * NB + grow) * A_DIM + 4];
        ma8[0]=m0.x; ma8[1]=m0.y; ma8[2]=m0.z; ma8[3]=m0.w;
        ma8[4]=m1.x; ma8[5]=m1.y; ma8[6]=m1.z; ma8[7]=m1.w;
    }
#pragma unroll
    for (int u = 0; u < 8; u++) {
        const int jc = kh + u;
        float ghr = pool[lr * WSP + jc]      + bgs[jc];
        float ghz = pool[lr * WSP + 16 + jc] + bgs[16 + jc];
        float ghn = pool[lr * WSP + 32 + jc] + bgs[32 + jc];
        float ir, iz, in_;
        if (!isp) {
            ir  = gi[jc];
            iz  = gi[512 + jc];
            in_ = gi[1024 + jc];
        } else {
            ir = bip[jc]; iz = bip[16 + jc]; in_ = bip[32 + jc];
#pragma unroll
            for (int a = 0; a < 8; a++) {
                ir  += ma8[a] * wp[jc * 8 + a];
                iz  += ma8[a] * wp[(16 + jc) * 8 + a];
                in_ += ma8[a] * wp[(32 + jc) * 8 + a];
            }
        }
        float r  = sigmoidf_(ir + ghr);
        float z  = sigmoidf_(iz + ghz);
        float nn = tanhf(in_ + r * ghn);
        float hv = hrow[j0 + jc];
        float hin = isp ? (hv * mr + grw[j0 + jc] * omr) : (hv * mr);
        hout[(size_t)grow * H_DIM + j0 + jc] = (1.0f - z) * nn + z * hin;
    }
}

// ---------------------------------------------------------------------------
// Launch
// ---------------------------------------------------------------------------
extern "C" void kernel_launch(void* const* d_in, const int* in_sizes, int n_in,
                              void* d_out, int out_size) {
    const float* x        = (const float*)d_in[0];
    const float* hxs      = (const float*)d_in[1];
    const float* hys      = (const float*)d_in[2];
    const float* gru_init = (const float*)d_in[3];
    const float* masks    = (const float*)d_in[4];
    const float* pa       = (const float*)d_in[5];
    const float* w_ih     = (const float*)d_in[6];
    const float* w_hh     = (const float*)d_in[7];
    const float* b_ih     = (const float*)d_in[8];
    const float* b_hh     = (const float*)d_in[9];
    const float* w_ih_p   = (const float*)d_in[10];
    const float* w_hh_p   = (const float*)d_in[11];
    const float* b_ih_p   = (const float*)d_in[12];
    const float* b_hh_p   = (const float*)d_in[13];

    float* out      = (float*)d_out;
    float* outs     = out;                                   // (TN, H)
    float* hxs_out  = outs + (size_t)TN * H_DIM;             // (N, H)
    float* outs_p   = hxs_out + (size_t)NB * H_DIM;          // (TN, H)
    float* hys_out  = outs_p + (size_t)TN * H_DIM;           // (N, H)

    // 1) masked prev-action
    ma_kernel<<<(TN * A_DIM + 255) / 256, 256>>>(pa, masks);

    // 2) big input GEMM (proven): g_GI = concat(x, ma) @ w_ih^T + b_ih
    gemm_input_kernel<<<dim3(G3 / 64, TN / 64), 128>>>(x, w_ih, b_ih);

    // 3) sequential scan, one fused kernel per step
    const float* hx_prev = hxs;
    const float* hy_prev = hys;
    for (int t = 0; t < T_STEPS; t++) {
        const float* masks_t = masks + (size_t)t * NB;
        const float* g_t     = gru_init + (size_t)t * NB * H_DIM;
        float* hx_out = outs   + (size_t)t * NB * H_DIM;
        float* hy_out = outs_p + (size_t)t * NB * H_DIM;

        step_kernel<<<128, 256>>>(t, hx_prev, hy_prev, masks_t, g_t,
                                  w_hh, w_hh_p, b_hh, b_hh_p,
                                  w_ih_p, b_ih_p,
                                  hx_out, hy_out);
        hx_prev = hx_out;
        hy_prev = hy_out;
    }

    // 4) final hidden states = last timestep outputs
    cudaMemcpyAsync(hxs_out, outs   + (size_t)(T_STEPS - 1) * NB * H_DIM,
                    (size_t)NB * H_DIM * sizeof(float), cudaMemcpyDeviceToDevice);
    cudaMemcpyAsync(hys_out, outs_p + (size_t)(T_STEPS - 1) * NB * H_DIM,
                    (size_t)NB * H_DIM * sizeof(float), cudaMemcpyDeviceToDevice);
}

// round 7
// speedup vs baseline: 1.8635x; 1.1339x over previous
#include <cuda_runtime.h>
#include <cuda_bf16.h>
#include <mma.h>
#include <math.h>

using namespace nvcuda;

#define T_STEPS 128
#define NB      256
#define E_DIM   512
#define A_DIM   8
#define H_DIM   512
#define G3      1536
#define TN      (T_STEPS * NB)
#define K_IN    (E_DIM + A_DIM)

// ---- scratch (device globals; no dynamic allocation allowed) ----
__device__ float g_GI[(size_t)TN * G3];   // input-side gates for gru (192 MiB)
__device__ float g_MA[TN * A_DIM];        // masked prev action

__device__ __forceinline__ float sigmoidf_(float x) { return 1.0f / (1.0f + expf(-x)); }

__device__ __forceinline__ void split_bf16(float v, __nv_bfloat16& hi, __nv_bfloat16& lo) {
    hi = __float2bfloat16(v);
    lo = __float2bfloat16(v - __bfloat162float(hi));
}

// ---------------------------------------------------------------------------
// Prep: ma[t,n,a] = prev_action_one_hot[t,n,a] * masks[t*N+n]   (proven)
// ---------------------------------------------------------------------------
__global__ void ma_kernel(const float* __restrict__ pa, const float* __restrict__ masks) {
    int i = blockIdx.x * blockDim.x + threadIdx.x;
    if (i < TN * A_DIM) g_MA[i] = pa[i] * masks[i >> 3];
}

// ---------------------------------------------------------------------------
// Big input GEMM (proven): GI[m, j] = sum_k X2[m,k]*w_ih[j,k] + b_ih[j]
// ---------------------------------------------------------------------------
__global__ void __launch_bounds__(128)
gemm_input_kernel(const float* __restrict__ x, const float* __restrict__ w_ih,
                  const float* __restrict__ b_ih) {
    __shared__ float As[16][65];
    __shared__ float Bs[16][65];
    const int j0  = blockIdx.x * 64;
    const int m0  = blockIdx.y * 64;
    const int tid = threadIdx.x;
    const int tx  = tid & 15;
    const int ty  = tid >> 4;
    const int lr  = tid >> 1;
    const int lk  = (tid & 1) * 8;

    float acc[8][4];
#pragma unroll
    for (int i = 0; i < 8; i++)
#pragma unroll
        for (int c = 0; c < 4; c++) acc[i][c] = 0.0f;

    const int m = m0 + lr;
    const int j = j0 + lr;

    for (int k0 = 0; k0 < K_IN; k0 += 16) {
#pragma unroll
        for (int u = 0; u < 8; u++) {
            int k = k0 + lk + u;
            float v = 0.0f;
            if (k < E_DIM)      v = x[(size_t)m * E_DIM + k];
            else if (k < K_IN)  v = g_MA[m * A_DIM + (k - E_DIM)];
            As[lk + u][lr] = v;
        }
#pragma unroll
        for (int u = 0; u < 8; u++) {
            int k = k0 + lk + u;
            float v = (k < K_IN) ? w_ih[(size_t)j * K_IN + k] : 0.0f;
            Bs[lk + u][lr] = v;
        }
        __syncthreads();
#pragma unroll
        for (int kk = 0; kk < 16; kk++) {
            float a[8], b[4];
#pragma unroll
            for (int i = 0; i < 8; i++) a[i] = As[kk][ty * 8 + i];
#pragma unroll
            for (int c = 0; c < 4; c++) b[c] = Bs[kk][tx * 4 + c];
#pragma unroll
            for (int i = 0; i < 8; i++)
#pragma unroll
                for (int c = 0; c < 4; c++) acc[i][c] += a[i] * b[c];
        }
        __syncthreads();
    }

#pragma unroll
    for (int i = 0; i < 8; i++) {
        int row = m0 + ty * 8 + i;
#pragma unroll
        for (int c = 0; c < 4; c++) {
            int col = j0 + tx * 4 + c;
            g_GI[(size_t)row * G3 + col] = acc[i][c] + b_ih[col];
        }
    }
}

// ---------------------------------------------------------------------------
// Fused step kernel: bf16x3 wmma hidden GEMM + round-6 fp32 gate epilogue.
// 128 CTAs x 256 threads. cta -> (gru, 16-col j-slice, 128-row half).
// Warp w owns rows w*16..w*16+15, all 3 gate tiles. K=512 in 16-chunks.
// ---------------------------------------------------------------------------
#define SP  24   // bf16 staging pitch
#define WSP 56   // C pitch (floats)

__global__ void __launch_bounds__(256)
step_kernel(int t,
            const float* __restrict__ hx_prev, const float* __restrict__ hy_prev,
            const float* __restrict__ masks_t, const float* __restrict__ g_t,
            const float* __restrict__ w_hh, const float* __restrict__ w_hh_p,
            const float* __restrict__ b_hh, const float* __restrict__ b_hh_p,
            const float* __restrict__ w_ih_p, const float* __restrict__ b_ih_p,
            float* __restrict__ hx_out, float* __restrict__ hy_out) {
    __shared__ __align__(32) float pool[128 * WSP];   // staging overlay, then C
    __shared__ float wp[48 * 8];
    __shared__ float bgs[48];
    __shared__ float bip[48];

    __nv_bfloat16* Ahi = (__nv_bfloat16*)pool;        // [128][SP]
    __nv_bfloat16* Alo = Ahi + 128 * SP;
    __nv_bfloat16* Whi = Alo + 128 * SP;              // [48][SP]
    __nv_bfloat16* Wlo = Whi + 48 * SP;

    const int cta = blockIdx.x;
    const bool isp = (cta >= 64);
    const int q = cta & 63;
    const int j0 = (q >> 1) * 16;
    const int mbase = (q & 1) * 128;

    const float* __restrict__ Wg = isp ? w_hh_p : w_hh;
    const float* __restrict__ bh = isp ? b_hh_p : b_hh;
    const float* __restrict__ hp = isp ? hy_prev : hx_prev;
    float* __restrict__ hout     = isp ? hy_out  : hx_out;

    const int tid = threadIdx.x;
    const int w = tid >> 5;
    // staging roles (round-6 proven index math)
    const int lr = tid >> 1;            // A row 0..127
    const int kh = (tid & 1) * 8;       // A k-half
    const int sW = tid >> 2;            // W s-row (valid tid<192)
    const int segW = (tid & 3) * 4;     // W k-segment

    const int grow = mbase + lr;
    const float mr = masks_t[grow];
    const float omr = 1.0f - mr;
    const float* __restrict__ hrow = hp  + (size_t)grow * H_DIM;
    const float* __restrict__ grw  = g_t + (size_t)grow * H_DIM;

    // stage biases + gru_p input weights (straight-line, pre-first-sync)
    if (tid < 48) {
        const int gidx = (tid >> 4) * H_DIM + j0 + (tid & 15);
        bgs[tid] = bh[gidx];
        bip[tid] = b_ih_p[gidx];
    }
    if (tid < 96) {
        const int s = tid >> 1, hf = (tid & 1) * 4;
        const int gidx = (s >> 4) * H_DIM + j0 + (s & 15);
        *(float4*)&wp[s * 8 + hf] = *(const float4*)&w_ih_p[(size_t)gidx * A_DIM + hf];
    }

    const int wrow = (sW >> 4) * H_DIM + j0 + (sW & 15);
    const float* __restrict__ Wrow = Wg + (size_t)wrow * H_DIM;

    wmma::fragment<wmma::accumulator, 16, 16, 16, float> acc[3];
#pragma unroll
    for (int g = 0; g < 3; g++) wmma::fill_fragment(acc[g], 0.0f);

    // prefetch chunk 0 (round-6 proven A math)
    float av[8];
    float4 wv;
    {
        float4 h0 = *(const float4*)(hrow + kh);
        float4 h1 = *(const float4*)(hrow + kh + 4);
        av[0]=h0.x; av[1]=h0.y; av[2]=h0.z; av[3]=h0.w;
        av[4]=h1.x; av[5]=h1.y; av[6]=h1.z; av[7]=h1.w;
        if (isp) {
            float4 g0 = *(const float4*)(grw + kh);
            float4 g1 = *(const float4*)(grw + kh + 4);
            float gv[8] = {g0.x,g0.y,g0.z,g0.w,g1.x,g1.y,g1.z,g1.w};
#pragma unroll
            for (int u = 0; u < 8; u++) av[u] = av[u] * mr + gv[u] * omr;
        } else {
#pragma unroll
            for (int u = 0; u < 8; u++) av[u] = av[u] * mr;
        }
        if (tid < 192) wv = *(const float4*)(Wrow + segW);
    }

    for (int ch = 0; ch < 32; ch++) {
        // store staged regs to smem as bf16 hi/lo
#pragma unroll
        for (int u = 0; u < 8; u++) {
            __nv_bfloat16 hi, lo;
            split_bf16(av[u], hi, lo);
            Ahi[lr * SP + kh + u] = hi;
            Alo[lr * SP + kh + u] = lo;
        }
        if (tid < 192) {
            float wvv[4] = {wv.x, wv.y, wv.z, wv.w};
#pragma unroll
            for (int u = 0; u < 4; u++) {
                __nv_bfloat16 hi, lo;
                split_bf16(wvv[u], hi, lo);
                Whi[sW * SP + segW + u] = hi;
                Wlo[sW * SP + segW + u] = lo;
            }
        }
        __syncthreads();

        // prefetch next chunk while computing this one
        if (ch < 31) {
            const int kb = (ch + 1) * 16 + kh;
            float4 h0 = *(const float4*)(hrow + kb);
            float4 h1 = *(const float4*)(hrow + kb + 4);
            av[0]=h0.x; av[1]=h0.y; av[2]=h0.z; av[3]=h0.w;
            av[4]=h1.x; av[5]=h1.y; av[6]=h1.z; av[7]=h1.w;
            if (isp) {
                float4 g0 = *(const float4*)(grw + kb);
                float4 g1 = *(const float4*)(grw + kb + 4);
                float gv[8] = {g0.x,g0.y,g0.z,g0.w,g1.x,g1.y,g1.z,g1.w};
#pragma unroll
                for (int u = 0; u < 8; u++) av[u] = av[u] * mr + gv[u] * omr;
            } else {
#pragma unroll
                for (int u = 0; u < 8; u++) av[u] = av[u] * mr;
            }
            if (tid < 192) wv = *(const float4*)(Wrow + (ch + 1) * 16 + segW);
        }

        // wmma: warp w -> rows w*16..+15, 3 gate tiles
        {
            wmma::fragment<wmma::matrix_a, 16, 16, 16, __nv_bfloat16, wmma::row_major> ahiF, aloF;
            wmma::load_matrix_sync(ahiF, &Ahi[(w * 16) * SP], SP);
            wmma::load_matrix_sync(aloF, &Alo[(w * 16) * SP], SP);
#pragma unroll
            for (int g = 0; g < 3; g++) {
                wmma::fragment<wmma::matrix_b, 16, 16, 16, __nv_bfloat16, wmma::col_major> bhiF, bloF;
                wmma::load_matrix_sync(bhiF, &Whi[(g * 16) * SP], SP);
                wmma::load_matrix_sync(bloF, &Wlo[(g * 16) * SP], SP);
                wmma::mma_sync(acc[g], ahiF, bhiF, acc[g]);
                wmma::mma_sync(acc[g], ahiF, bloF, acc[g]);
                wmma::mma_sync(acc[g], aloF, bhiF, acc[g]);
            }
        }
        __syncthreads();
    }

    // ---- write C to smem (overlays staging; all staging reads complete) ----
#pragma unroll
    for (int g = 0; g < 3; g++)
        wmma::store_matrix_sync(&pool[(w * 16) * WSP + g * 16], acc[g], WSP,
                                wmma::mem_row_major);
    __syncthreads();

    // ---- fused gate epilogue (round-6 verbatim): row lr, cols kh..kh+7 ----
    const float* __restrict__ gi = g_GI + ((size_t)t * NB + grow) * G3 + j0;
    float ma8[8];
    if (isp) {
        float4 m0 = *(const float4*)&g_MA[((size_t)t * NB + grow) * A_DIM];
        float4 m1 = *(const float4*)&g_MA[((size_t)t * NB + grow) * A_DIM + 4];
        ma8[0]=m0.x; ma8[1]=m0.y; ma8[2]=m0.z; ma8[3]=m0.w;
        ma8[4]=m1.x; ma8[5]=m1.y; ma8[6]=m1.z; ma8[7]=m1.w;
    }
#pragma unroll
    for (int u = 0; u < 8; u++) {
        const int jc = kh + u;
        float ghr = pool[lr * WSP + jc]      + bgs[jc];
        float ghz = pool[lr * WSP + 16 + jc] + bgs[16 + jc];
        float ghn = pool[lr * WSP + 32 + jc] + bgs[32 + jc];
        float ir, iz, in_;
        if (!isp) {
            ir  = gi[jc];
            iz  = gi[512 + jc];
            in_ = gi[1024 + jc];
        } else {
            ir = bip[jc]; iz = bip[16 + jc]; in_ = bip[32 + jc];
#pragma unroll
            for (int a = 0; a < 8; a++) {
                ir  += ma8[a] * wp[jc * 8 + a];
                iz  += ma8[a] * wp[(16 + jc) * 8 + a];
                in_ += ma8[a] * wp[(32 + jc) * 8 + a];
            }
        }
        float r  = sigmoidf_(ir + ghr);
        float z  = sigmoidf_(iz + ghz);
        float nn = tanhf(in_ + r * ghn);
        float hv = hrow[j0 + jc];
        float hin = isp ? (hv * mr + grw[j0 + jc] * omr) : (hv * mr);
        hout[(size_t)grow * H_DIM + j0 + jc] = (1.0f - z) * nn + z * hin;
    }
}

// ---------------------------------------------------------------------------
// Launch
// ---------------------------------------------------------------------------
extern "C" void kernel_launch(void* const* d_in, const int* in_sizes, int n_in,
                              void* d_out, int out_size) {
    const float* x        = (const float*)d_in[0];
    const float* hxs      = (const float*)d_in[1];
    const float* hys      = (const float*)d_in[2];
    const float* gru_init = (const float*)d_in[3];
    const float* masks    = (const float*)d_in[4];
    const float* pa       = (const float*)d_in[5];
    const float* w_ih     = (const float*)d_in[6];
    const float* w_hh     = (const float*)d_in[7];
    const float* b_ih     = (const float*)d_in[8];
    const float* b_hh     = (const float*)d_in[9];
    const float* w_ih_p   = (const float*)d_in[10];
    const float* w_hh_p   = (const float*)d_in[11];
    const float* b_ih_p   = (const float*)d_in[12];
    const float* b_hh_p   = (const float*)d_in[13];

    float* out      = (float*)d_out;
    float* outs     = out;                                   // (TN, H)
    float* hxs_out  = outs + (size_t)TN * H_DIM;             // (N, H)
    float* outs_p   = hxs_out + (size_t)NB * H_DIM;          // (TN, H)
    float* hys_out  = outs_p + (size_t)TN * H_DIM;           // (N, H)

    // 1) masked prev-action
    ma_kernel<<<(TN * A_DIM + 255) / 256, 256>>>(pa, masks);

    // 2) big input GEMM (proven): g_GI = concat(x, ma) @ w_ih^T + b_ih
    gemm_input_kernel<<<dim3(G3 / 64, TN / 64), 128>>>(x, w_ih, b_ih);

    // 3) sequential scan, one fused kernel per step
    const float* hx_prev = hxs;
    const float* hy_prev = hys;
    for (int t = 0; t < T_STEPS; t++) {
        const float* masks_t = masks + (size_t)t * NB;
        const float* g_t     = gru_init + (size_t)t * NB * H_DIM;
        float* hx_out = outs   + (size_t)t * NB * H_DIM;
        float* hy_out = outs_p + (size_t)t * NB * H_DIM;

        step_kernel<<<128, 256>>>(t, hx_prev, hy_prev, masks_t, g_t,
                                  w_hh, w_hh_p, b_hh, b_hh_p,
                                  w_ih_p, b_ih_p,
                                  hx_out, hy_out);
        hx_prev = hx_out;
        hy_prev = hy_out;
    }

    // 4) final hidden states = last timestep outputs
    cudaMemcpyAsync(hxs_out, outs   + (size_t)(T_STEPS - 1) * NB * H_DIM,
                    (size_t)NB * H_DIM * sizeof(float), cudaMemcpyDeviceToDevice);
    cudaMemcpyAsync(hys_out, outs_p + (size_t)(T_STEPS - 1) * NB * H_DIM,
                    (size_t)NB * H_DIM * sizeof(float), cudaMemcpyDeviceToDevice);
}

// round 8
// speedup vs baseline: 2.4057x; 1.2910x over previous
#include <cuda_runtime.h>
#include <cuda_bf16.h>
#include <mma.h>
#include <math.h>
#include <stdint.h>

using namespace nvcuda;

#define T_STEPS 128
#define NB      256
#define E_DIM   512
#define A_DIM   8
#define H_DIM   512
#define G3      1536
#define TN      (T_STEPS * NB)
#define K_IN    (E_DIM + A_DIM)

// ---- scratch (device globals; no dynamic allocation allowed) ----
__device__ float g_GI[(size_t)TN * G3];   // input-side gates for gru (192 MiB)
__device__ float g_MA[TN * A_DIM];        // masked prev action

// pre-split bf16 weights (hi/lo)
__device__ __nv_bfloat16 g_Wih_hi[G3 * K_IN],  g_Wih_lo[G3 * K_IN];
__device__ __nv_bfloat16 g_Whh_hi[G3 * H_DIM], g_Whh_lo[G3 * H_DIM];
__device__ __nv_bfloat16 g_Whp_hi[G3 * H_DIM], g_Whp_lo[G3 * H_DIM];

__device__ __forceinline__ float sigmoidf_(float x) { return 1.0f / (1.0f + expf(-x)); }

__device__ __forceinline__ void split_bf16(float v, __nv_bfloat16& hi, __nv_bfloat16& lo) {
    hi = __float2bfloat16(v);
    lo = __float2bfloat16(v - __bfloat162float(hi));
}

// ---------------------------------------------------------------------------
// Prep: ma[t,n,a] = prev_action_one_hot[t,n,a] * masks[t*N+n]   (proven)
// ---------------------------------------------------------------------------
__global__ void ma_kernel(const float* __restrict__ pa, const float* __restrict__ masks) {
    int i = blockIdx.x * blockDim.x + threadIdx.x;
    if (i < TN * A_DIM) g_MA[i] = pa[i] * masks[i >> 3];
}

// ---------------------------------------------------------------------------
// Prep: split all weights into bf16 hi/lo global buffers (one launch).
// ---------------------------------------------------------------------------
__global__ void split3_kernel(const float* __restrict__ w_ih,
                              const float* __restrict__ w_hh,
                              const float* __restrict__ w_hh_p) {
    int i = blockIdx.x * blockDim.x + threadIdx.x;
    if (i < G3 * K_IN) {
        __nv_bfloat16 hi, lo;
        split_bf16(w_ih[i], hi, lo);
        g_Wih_hi[i] = hi; g_Wih_lo[i] = lo;
    }
    if (i < G3 * H_DIM) {
        __nv_bfloat16 hi, lo;
        split_bf16(w_hh[i], hi, lo);
        g_Whh_hi[i] = hi; g_Whh_lo[i] = lo;
        split_bf16(w_hh_p[i], hi, lo);
        g_Whp_hi[i] = hi; g_Whp_lo[i] = lo;
    }
}

// ---------------------------------------------------------------------------
// Input GEMM (bf16x3 wmma): g_GI[m, gate*512+j0+jc] = bias + sum_k X2[m,k]*w_ih[row,k]
// CTA: 256 rows x 48 gate-cols (16-col j-slice x 3 gates), K=520 in 33 chunks of 16
// (chunk 32 = MA tail, zero-padded). Bias pre-loaded into accumulators.
// grid: (32, 128), 256 threads (8 warps, warp w -> rows w*32..w*32+31).
// ---------------------------------------------------------------------------
#define SP 24    // bf16 staging pitch for K16 chunks

__global__ void __launch_bounds__(256)
input_gemm_kernel(const float* __restrict__ X, const float* __restrict__ b_ih) {
    __shared__ __nv_bfloat16 Ahi[256 * SP], Alo[256 * SP];
    __shared__ __nv_bfloat16 Whi[48 * SP],  Wlo[48 * SP];
    __shared__ float btile[16 * 48];

    const int j0 = blockIdx.x * 16;
    const int m0 = blockIdx.y * 256;
    const int tid = threadIdx.x;
    const int w = tid >> 5;

    // A role: thread = one row, all 16 k of the chunk
    const int m = m0 + tid;
    const float* __restrict__ Xr = X + (size_t)m * E_DIM;
    // W role: tid<192, 4 threads per s-row, 4 k each
    const int sW = tid >> 2;
    const int segW = (tid & 3) * 4;
    const int wrow = (sW >> 4) * H_DIM + j0 + (sW & 15);   // w_ih row (length K_IN)

    // bias tile: 16 identical rows of the 48 gate-col biases
    for (int i = tid; i < 16 * 48; i += 256) {
        int c = i % 48;
        btile[i] = b_ih[(c >> 4) * H_DIM + j0 + (c & 15)];
    }
    __syncthreads();

    wmma::fragment<wmma::accumulator, 16, 16, 16, float> acc[2][3];
#pragma unroll
    for (int rt = 0; rt < 2; rt++)
#pragma unroll
        for (int g = 0; g < 3; g++)
            wmma::load_matrix_sync(acc[rt][g], &btile[g * 16], 48, wmma::mem_row_major);
    __syncthreads();

    for (int ch = 0; ch < 33; ch++) {
        // stage A
        float av[16];
        if (ch < 32) {
            const int kb = ch * 16;
            float4 a0 = *(const float4*)(Xr + kb);
            float4 a1 = *(const float4*)(Xr + kb + 4);
            float4 a2 = *(const float4*)(Xr + kb + 8);
            float4 a3 = *(const float4*)(Xr + kb + 12);
            av[0]=a0.x; av[1]=a0.y; av[2]=a0.z;  av[3]=a0.w;
            av[4]=a1.x; av[5]=a1.y; av[6]=a1.z;  av[7]=a1.w;
            av[8]=a2.x; av[9]=a2.y; av[10]=a2.z; av[11]=a2.w;
            av[12]=a3.x; av[13]=a3.y; av[14]=a3.z; av[15]=a3.w;
        } else {
            float4 m0v = *(const float4*)&g_MA[(size_t)m * A_DIM];
            float4 m1v = *(const float4*)&g_MA[(size_t)m * A_DIM + 4];
            av[0]=m0v.x; av[1]=m0v.y; av[2]=m0v.z; av[3]=m0v.w;
            av[4]=m1v.x; av[5]=m1v.y; av[6]=m1v.z; av[7]=m1v.w;
#pragma unroll
            for (int u = 8; u < 16; u++) av[u] = 0.0f;
        }
#pragma unroll
        for (int u = 0; u < 16; u++) {
            __nv_bfloat16 hi, lo;
            split_bf16(av[u], hi, lo);
            Ahi[tid * SP + u] = hi;
            Alo[tid * SP + u] = lo;
        }
        // stage W (pre-split bf16; tail pad: k>=520 -> zeros)
        if (tid < 192) {
            const bool pad = (ch == 32) && (segW >= 8);
            const size_t off = (size_t)wrow * K_IN + ch * 16 + segW;
            uint2 hv = pad ? make_uint2(0, 0) : *(const uint2*)(g_Wih_hi + off);
            uint2 lv = pad ? make_uint2(0, 0) : *(const uint2*)(g_Wih_lo + off);
            *(uint2*)&Whi[sW * SP + segW] = hv;
            *(uint2*)&Wlo[sW * SP + segW] = lv;
        }
        __syncthreads();

#pragma unroll
        for (int rt = 0; rt < 2; rt++) {
            wmma::fragment<wmma::matrix_a, 16, 16, 16, __nv_bfloat16, wmma::row_major> ahiF, aloF;
            wmma::load_matrix_sync(ahiF, &Ahi[(w * 32 + rt * 16) * SP], SP);
            wmma::load_matrix_sync(aloF, &Alo[(w * 32 + rt * 16) * SP], SP);
#pragma unroll
            for (int g = 0; g < 3; g++) {
                wmma::fragment<wmma::matrix_b, 16, 16, 16, __nv_bfloat16, wmma::col_major> bhiF, bloF;
                wmma::load_matrix_sync(bhiF, &Whi[(g * 16) * SP], SP);
                wmma::load_matrix_sync(bloF, &Wlo[(g * 16) * SP], SP);
                wmma::mma_sync(acc[rt][g], ahiF, bhiF, acc[rt][g]);
                wmma::mma_sync(acc[rt][g], ahiF, bloF, acc[rt][g]);
                wmma::mma_sync(acc[rt][g], aloF, bhiF, acc[rt][g]);
            }
        }
        __syncthreads();
    }

    // store directly to g_GI (bias already in acc)
#pragma unroll
    for (int rt = 0; rt < 2; rt++)
#pragma unroll
        for (int g = 0; g < 3; g++) {
            int row0 = m0 + w * 32 + rt * 16;
            int col0 = g * H_DIM + j0;
            wmma::store_matrix_sync(g_GI + (size_t)row0 * G3 + col0, acc[rt][g], G3,
                                    wmma::mem_row_major);
        }
}

// ---------------------------------------------------------------------------
// Fused step kernel: bf16x3 wmma hidden GEMM + fp32 gate epilogue (round-7).
// K-chunk 32 (16 chunks, 32 syncs); W staged as pure copies from pre-split bf16.
// 128 CTAs x 256 threads. cta -> (gru, 16-col j-slice, 128-row half).
// ---------------------------------------------------------------------------
#define SP2 40   // bf16 staging pitch for K32 chunks
#define WSP 56   // C pitch (floats)

__global__ void __launch_bounds__(256)
step_kernel(int t,
            const float* __restrict__ hx_prev, const float* __restrict__ hy_prev,
            const float* __restrict__ masks_t, const float* __restrict__ g_t,
            const float* __restrict__ b_hh, const float* __restrict__ b_hh_p,
            const float* __restrict__ w_ih_p, const float* __restrict__ b_ih_p,
            float* __restrict__ hx_out, float* __restrict__ hy_out) {
    __shared__ __align__(16) float pool[128 * WSP];   // staging overlay, then C
    __shared__ float wp[48 * 8];
    __shared__ float bgs[48];
    __shared__ float bip[48];

    __nv_bfloat16* Ahi = (__nv_bfloat16*)pool;        // [128][SP2]
    __nv_bfloat16* Alo = Ahi + 128 * SP2;
    __nv_bfloat16* Whi = Alo + 128 * SP2;             // [48][SP2]
    __nv_bfloat16* Wlo = Whi + 48 * SP2;

    const int cta = blockIdx.x;
    const bool isp = (cta >= 64);
    const int q = cta & 63;
    const int j0 = (q >> 1) * 16;
    const int mbase = (q & 1) * 128;

    const __nv_bfloat16* __restrict__ WhiG = isp ? g_Whp_hi : g_Whh_hi;
    const __nv_bfloat16* __restrict__ WloG = isp ? g_Whp_lo : g_Whh_lo;
    const float* __restrict__ bh = isp ? b_hh_p : b_hh;
    const float* __restrict__ hp = isp ? hy_prev : hx_prev;
    float* __restrict__ hout     = isp ? hy_out  : hx_out;

    const int tid = threadIdx.x;
    const int w = tid >> 5;
    // staging roles
    const int lr  = tid >> 1;           // A row 0..127
    const int kh2 = (tid & 1) * 16;     // A k-half (0 or 16)
    const int kh  = (tid & 1) * 8;      // epilogue col-half (round-7 contract)
    const int sW  = tid >> 2;           // W s-row (valid tid<192)
    const int segW8 = (tid & 3) * 8;    // W k-segment (8 wide)

    const int grow = mbase + lr;
    const float mr = masks_t[grow];
    const float omr = 1.0f - mr;
    const float* __restrict__ hrow = hp  + (size_t)grow * H_DIM;
    const float* __restrict__ grw  = g_t + (size_t)grow * H_DIM;

    // stage biases + gru_p input weights (straight-line, pre-first-sync)
    if (tid < 48) {
        const int gidx = (tid >> 4) * H_DIM + j0 + (tid & 15);
        bgs[tid] = bh[gidx];
        bip[tid] = b_ih_p[gidx];
    }
    if (tid < 96) {
        const int s = tid >> 1, hf = (tid & 1) * 4;
        const int gidx = (s >> 4) * H_DIM + j0 + (s & 15);
        *(float4*)&wp[s * 8 + hf] = *(const float4*)&w_ih_p[(size_t)gidx * A_DIM + hf];
    }

    const int wrow = (sW >> 4) * H_DIM + j0 + (sW & 15);
    const __nv_bfloat16* __restrict__ WhiR = WhiG + (size_t)wrow * H_DIM;
    const __nv_bfloat16* __restrict__ WloR = WloG + (size_t)wrow * H_DIM;

    wmma::fragment<wmma::accumulator, 16, 16, 16, float> acc[3];
#pragma unroll
    for (int g = 0; g < 3; g++) wmma::fill_fragment(acc[g], 0.0f);

    // prefetch chunk 0
    float av[16];
    uint4 whv, wlv;
    {
        float4 h0 = *(const float4*)(hrow + kh2);
        float4 h1 = *(const float4*)(hrow + kh2 + 4);
        float4 h2 = *(const float4*)(hrow + kh2 + 8);
        float4 h3 = *(const float4*)(hrow + kh2 + 12);
        av[0]=h0.x; av[1]=h0.y; av[2]=h0.z;  av[3]=h0.w;
        av[4]=h1.x; av[5]=h1.y; av[6]=h1.z;  av[7]=h1.w;
        av[8]=h2.x; av[9]=h2.y; av[10]=h2.z; av[11]=h2.w;
        av[12]=h3.x; av[13]=h3.y; av[14]=h3.z; av[15]=h3.w;
        if (isp) {
            float4 g0 = *(const float4*)(grw + kh2);
            float4 g1 = *(const float4*)(grw + kh2 + 4);
            float4 g2 = *(const float4*)(grw + kh2 + 8);
            float4 g3 = *(const float4*)(grw + kh2 + 12);
            float gv[16] = {g0.x,g0.y,g0.z,g0.w, g1.x,g1.y,g1.z,g1.w,
                            g2.x,g2.y,g2.z,g2.w, g3.x,g3.y,g3.z,g3.w};
#pragma unroll
            for (int u = 0; u < 16; u++) av[u] = av[u] * mr + gv[u] * omr;
        } else {
#pragma unroll
            for (int u = 0; u < 16; u++) av[u] = av[u] * mr;
        }
        if (tid < 192) {
            whv = *(const uint4*)(WhiR + segW8);
            wlv = *(const uint4*)(WloR + segW8);
        }
    }

    for (int ch = 0; ch < 16; ch++) {
        // store staged regs to smem
#pragma unroll
        for (int u = 0; u < 16; u++) {
            __nv_bfloat16 hi, lo;
            split_bf16(av[u], hi, lo);
            Ahi[lr * SP2 + kh2 + u] = hi;
            Alo[lr * SP2 + kh2 + u] = lo;
        }
        if (tid < 192) {
            *(uint4*)&Whi[sW * SP2 + segW8] = whv;
            *(uint4*)&Wlo[sW * SP2 + segW8] = wlv;
        }
        __syncthreads();

        // prefetch next chunk while computing this one
        if (ch < 15) {
            const int kb = (ch + 1) * 32 + kh2;
            float4 h0 = *(const float4*)(hrow + kb);
            float4 h1 = *(const float4*)(hrow + kb + 4);
            float4 h2 = *(const float4*)(hrow + kb + 8);
            float4 h3 = *(const float4*)(hrow + kb + 12);
            av[0]=h0.x; av[1]=h0.y; av[2]=h0.z;  av[3]=h0.w;
            av[4]=h1.x; av[5]=h1.y; av[6]=h1.z;  av[7]=h1.w;
            av[8]=h2.x; av[9]=h2.y; av[10]=h2.z; av[11]=h2.w;
            av[12]=h3.x; av[13]=h3.y; av[14]=h3.z; av[15]=h3.w;
            if (isp) {
                float4 g0 = *(const float4*)(grw + kb);
                float4 g1 = *(const float4*)(grw + kb + 4);
                float4 g2 = *(const float4*)(grw + kb + 8);
                float4 g3 = *(const float4*)(grw + kb + 12);
                float gv[16] = {g0.x,g0.y,g0.z,g0.w, g1.x,g1.y,g1.z,g1.w,
                                g2.x,g2.y,g2.z,g2.w, g3.x,g3.y,g3.z,g3.w};
#pragma unroll
                for (int u = 0; u < 16; u++) av[u] = av[u] * mr + gv[u] * omr;
            } else {
#pragma unroll
                for (int u = 0; u < 16; u++) av[u] = av[u] * mr;
            }
            if (tid < 192) {
                whv = *(const uint4*)(WhiR + (ch + 1) * 32 + segW8);
                wlv = *(const uint4*)(WloR + (ch + 1) * 32 + segW8);
            }
        }

        // wmma: warp w -> rows w*16..+15, 3 gate tiles, 2 k16 subtiles
#pragma unroll
        for (int k8 = 0; k8 < 2; k8++) {
            wmma::fragment<wmma::matrix_a, 16, 16, 16, __nv_bfloat16, wmma::row_major> ahiF, aloF;
            wmma::load_matrix_sync(ahiF, &Ahi[(w * 16) * SP2 + k8 * 16], SP2);
            wmma::load_matrix_sync(aloF, &Alo[(w * 16) * SP2 + k8 * 16], SP2);
#pragma unroll
            for (int g = 0; g < 3; g++) {
                wmma::fragment<wmma::matrix_b, 16, 16, 16, __nv_bfloat16, wmma::col_major> bhiF, bloF;
                wmma::load_matrix_sync(bhiF, &Whi[(g * 16) * SP2 + k8 * 16], SP2);
                wmma::load_matrix_sync(bloF, &Wlo[(g * 16) * SP2 + k8 * 16], SP2);
                wmma::mma_sync(acc[g], ahiF, bhiF, acc[g]);
                wmma::mma_sync(acc[g], ahiF, bloF, acc[g]);
                wmma::mma_sync(acc[g], aloF, bhiF, acc[g]);
            }
        }
        __syncthreads();
    }

    // ---- write C to smem (overlays staging; all staging reads complete) ----
#pragma unroll
    for (int g = 0; g < 3; g++)
        wmma::store_matrix_sync(&pool[(w * 16) * WSP + g * 16], acc[g], WSP,
                                wmma::mem_row_major);
    __syncthreads();

    // ---- fused gate epilogue (round-7 verbatim): row lr, cols kh..kh+7 ----
    const float* __restrict__ gi = g_GI + ((size_t)t * NB + grow) * G3 + j0;
    float ma8[8];
    if (isp) {
        float4 m0 = *(const float4*)&g_MA[((size_t)t * NB + grow) * A_DIM];
        float4 m1 = *(const float4*)&g_MA[((size_t)t * NB + grow) * A_DIM + 4];
        ma8[0]=m0.x; ma8[1]=m0.y; ma8[2]=m0.z; ma8[3]=m0.w;
        ma8[4]=m1.x; ma8[5]=m1.y; ma8[6]=m1.z; ma8[7]=m1.w;
    }
#pragma unroll
    for (int u = 0; u < 8; u++) {
        const int jc = kh + u;
        float ghr = pool[lr * WSP + jc]      + bgs[jc];
        float ghz = pool[lr * WSP + 16 + jc] + bgs[16 + jc];
        float ghn = pool[lr * WSP + 32 + jc] + bgs[32 + jc];
        float ir, iz, in_;
        if (!isp) {
            ir  = gi[jc];
            iz  = gi[512 + jc];
            in_ = gi[1024 + jc];
        } else {
            ir = bip[jc]; iz = bip[16 + jc]; in_ = bip[32 + jc];
#pragma unroll
            for (int a = 0; a < 8; a++) {
                ir  += ma8[a] * wp[jc * 8 + a];
                iz  += ma8[a] * wp[(16 + jc) * 8 + a];
                in_ += ma8[a] * wp[(32 + jc) * 8 + a];
            }
        }
        float r  = sigmoidf_(ir + ghr);
        float z  = sigmoidf_(iz + ghz);
        float nn = tanhf(in_ + r * ghn);
        float hv = hrow[j0 + jc];
        float hin = isp ? (hv * mr + grw[j0 + jc] * omr) : (hv * mr);
        hout[(size_t)grow * H_DIM + j0 + jc] = (1.0f - z) * nn + z * hin;
    }
}

// ---------------------------------------------------------------------------
// Launch
// ---------------------------------------------------------------------------
extern "C" void kernel_launch(void* const* d_in, const int* in_sizes, int n_in,
                              void* d_out, int out_size) {
    const float* x        = (const float*)d_in[0];
    const float* hxs      = (const float*)d_in[1];
    const float* hys      = (const float*)d_in[2];
    const float* gru_init = (const float*)d_in[3];
    const float* masks    = (const float*)d_in[4];
    const float* pa       = (const float*)d_in[5];
    const float* w_ih     = (const float*)d_in[6];
    const float* w_hh     = (const float*)d_in[7];
    const float* b_ih     = (const float*)d_in[8];
    const float* b_hh     = (const float*)d_in[9];
    const float* w_ih_p   = (const float*)d_in[10];
    const float* w_hh_p   = (const float*)d_in[11];
    const float* b_ih_p   = (const float*)d_in[12];
    const float* b_hh_p   = (const float*)d_in[13];

    float* out      = (float*)d_out;
    float* outs     = out;                                   // (TN, H)
    float* hxs_out  = outs + (size_t)TN * H_DIM;             // (N, H)
    float* outs_p   = hxs_out + (size_t)NB * H_DIM;          // (TN, H)
    float* hys_out  = outs_p + (size_t)TN * H_DIM;           // (N, H)

    // 1) masked prev-action + weight pre-split
    ma_kernel<<<(TN * A_DIM + 255) / 256, 256>>>(pa, masks);
    split3_kernel<<<(G3 * K_IN + 255) / 256, 256>>>(w_ih, w_hh, w_hh_p);

    // 2) big input GEMM (bf16x3 wmma, bias fused): g_GI complete
    input_gemm_kernel<<<dim3(G3 / 48, TN / 256), 256>>>(x, b_ih);

    // 3) sequential scan, one fused kernel per step
    const float* hx_prev = hxs;
    const float* hy_prev = hys;
    for (int t = 0; t < T_STEPS; t++) {
        const float* masks_t = masks + (size_t)t * NB;
        const float* g_t     = gru_init + (size_t)t * NB * H_DIM;
        float* hx_out = outs   + (size_t)t * NB * H_DIM;
        float* hy_out = outs_p + (size_t)t * NB * H_DIM;

        step_kernel<<<128, 256>>>(t, hx_prev, hy_prev, masks_t, g_t,
                                  b_hh, b_hh_p, w_ih_p, b_ih_p,
                                  hx_out, hy_out);
        hx_prev = hx_out;
        hy_prev = hy_out;
    }

    // 4) final hidden states = last timestep outputs
    cudaMemcpyAsync(hxs_out, outs   + (size_t)(T_STEPS - 1) * NB * H_DIM,
                    (size_t)NB * H_DIM * sizeof(float), cudaMemcpyDeviceToDevice);
    cudaMemcpyAsync(hys_out, outs_p + (size_t)(T_STEPS - 1) * NB * H_DIM,
                    (size_t)NB * H_DIM * sizeof(float), cudaMemcpyDeviceToDevice);
}

// round 9
// speedup vs baseline: 2.6883x; 1.1174x over previous
#include <cuda_runtime.h>
#include <cuda_bf16.h>
#include <mma.h>
#include <math.h>
#include <stdint.h>

using namespace nvcuda;

#define T_STEPS 128
#define NB      256
#define E_DIM   512
#define A_DIM   8
#define H_DIM   512
#define G3      1536
#define TN      (T_STEPS * NB)
#define K_IN    (E_DIM + A_DIM)

// ---- scratch (device globals; no dynamic allocation allowed) ----
__device__ float g_GI[(size_t)TN * G3];   // input-side gates for gru (192 MiB)
__device__ float g_MA[TN * A_DIM];        // masked prev action

// pre-split bf16 weights (hi/lo)
__device__ __nv_bfloat16 g_Wih_hi[G3 * K_IN],  g_Wih_lo[G3 * K_IN];
__device__ __nv_bfloat16 g_Whh_hi[G3 * H_DIM], g_Whh_lo[G3 * H_DIM];
__device__ __nv_bfloat16 g_Whp_hi[G3 * H_DIM], g_Whp_lo[G3 * H_DIM];

__device__ __forceinline__ float sigmoidf_(float x) { return 1.0f / (1.0f + expf(-x)); }

__device__ __forceinline__ void split_bf16(float v, __nv_bfloat16& hi, __nv_bfloat16& lo) {
    hi = __float2bfloat16(v);
    lo = __float2bfloat16(v - __bfloat162float(hi));
}

// pack 16 floats -> 2x uint4 hi + 2x uint4 lo stores (16B each)
__device__ __forceinline__ void store_split16(__nv_bfloat16* hiDst, __nv_bfloat16* loDst,
                                              const float av[16]) {
    __nv_bfloat162 hp[8], lp[8];
#pragma unroll
    for (int u = 0; u < 8; u++) {
        __nv_bfloat16 h0, l0, h1, l1;
        split_bf16(av[2 * u],     h0, l0);
        split_bf16(av[2 * u + 1], h1, l1);
        hp[u] = __halves2bfloat162(h0, h1);
        lp[u] = __halves2bfloat162(l0, l1);
    }
    *(uint4*)(hiDst)     = *(const uint4*)&hp[0];
    *(uint4*)(hiDst + 8) = *(const uint4*)&hp[4];
    *(uint4*)(loDst)     = *(const uint4*)&lp[0];
    *(uint4*)(loDst + 8) = *(const uint4*)&lp[4];
}

// ---------------------------------------------------------------------------
// Prep: ma[t,n,a] = prev_action_one_hot[t,n,a] * masks[t*N+n]   (proven)
// ---------------------------------------------------------------------------
__global__ void ma_kernel(const float* __restrict__ pa, const float* __restrict__ masks) {
    int i = blockIdx.x * blockDim.x + threadIdx.x;
    if (i < TN * A_DIM) g_MA[i] = pa[i] * masks[i >> 3];
}

// ---------------------------------------------------------------------------
// Prep: split all weights into bf16 hi/lo, 8 elements/thread, uint4 stores.
// ---------------------------------------------------------------------------
__global__ void split3_kernel(const float* __restrict__ w_ih,
                              const float* __restrict__ w_hh,
                              const float* __restrict__ w_hh_p) {
    int i8 = (blockIdx.x * blockDim.x + threadIdx.x) * 8;
    if (i8 < G3 * K_IN) {
        float4 v0 = *(const float4*)(w_ih + i8);
        float4 v1 = *(const float4*)(w_ih + i8 + 4);
        float v[8] = {v0.x, v0.y, v0.z, v0.w, v1.x, v1.y, v1.z, v1.w};
        __nv_bfloat162 hp[4], lp[4];
#pragma unroll
        for (int u = 0; u < 4; u++) {
            __nv_bfloat16 h0, l0, h1, l1;
            split_bf16(v[2 * u], h0, l0);
            split_bf16(v[2 * u + 1], h1, l1);
            hp[u] = __halves2bfloat162(h0, h1);
            lp[u] = __halves2bfloat162(l0, l1);
        }
        *(uint4*)&g_Wih_hi[i8] = *(const uint4*)&hp[0];
        *(uint4*)&g_Wih_lo[i8] = *(const uint4*)&lp[0];
    }
    if (i8 < G3 * H_DIM) {
        {
            float4 v0 = *(const float4*)(w_hh + i8);
            float4 v1 = *(const float4*)(w_hh + i8 + 4);
            float v[8] = {v0.x, v0.y, v0.z, v0.w, v1.x, v1.y, v1.z, v1.w};
            __nv_bfloat162 hp[4], lp[4];
#pragma unroll
            for (int u = 0; u < 4; u++) {
                __nv_bfloat16 h0, l0, h1, l1;
                split_bf16(v[2 * u], h0, l0);
                split_bf16(v[2 * u + 1], h1, l1);
                hp[u] = __halves2bfloat162(h0, h1);
                lp[u] = __halves2bfloat162(l0, l1);
            }
            *(uint4*)&g_Whh_hi[i8] = *(const uint4*)&hp[0];
            *(uint4*)&g_Whh_lo[i8] = *(const uint4*)&lp[0];
        }
        {
            float4 v0 = *(const float4*)(w_hh_p + i8);
            float4 v1 = *(const float4*)(w_hh_p + i8 + 4);
            float v[8] = {v0.x, v0.y, v0.z, v0.w, v1.x, v1.y, v1.z, v1.w};
            __nv_bfloat162 hp[4], lp[4];
#pragma unroll
            for (int u = 0; u < 4; u++) {
                __nv_bfloat16 h0, l0, h1, l1;
                split_bf16(v[2 * u], h0, l0);
                split_bf16(v[2 * u + 1], h1, l1);
                hp[u] = __halves2bfloat162(h0, h1);
                lp[u] = __halves2bfloat162(l0, l1);
            }
            *(uint4*)&g_Whp_hi[i8] = *(const uint4*)&hp[0];
            *(uint4*)&g_Whp_lo[i8] = *(const uint4*)&lp[0];
        }
    }
}

// ---------------------------------------------------------------------------
// Input GEMM (bf16x3 wmma): g_GI = bias + X2 @ w_ih^T   (round-8 proven; packed STS)
// CTA: 256 rows x 48 gate-cols, K=520 in 33 chunks of 16 (chunk 32 = MA tail).
// grid: (32, 128), 256 threads.
// ---------------------------------------------------------------------------
#define SP 24

__global__ void __launch_bounds__(256)
input_gemm_kernel(const float* __restrict__ X, const float* __restrict__ b_ih) {
    __shared__ __nv_bfloat16 Ahi[256 * SP], Alo[256 * SP];
    __shared__ __nv_bfloat16 Whi[48 * SP],  Wlo[48 * SP];
    __shared__ float btile[16 * 48];

    const int j0 = blockIdx.x * 16;
    const int m0 = blockIdx.y * 256;
    const int tid = threadIdx.x;
    const int w = tid >> 5;

    const int m = m0 + tid;
    const float* __restrict__ Xr = X + (size_t)m * E_DIM;
    const int sW = tid >> 2;
    const int segW = (tid & 3) * 4;
    const int wrow = (sW >> 4) * H_DIM + j0 + (sW & 15);

    for (int i = tid; i < 16 * 48; i += 256) {
        int c = i % 48;
        btile[i] = b_ih[(c >> 4) * H_DIM + j0 + (c & 15)];
    }
    __syncthreads();

    wmma::fragment<wmma::accumulator, 16, 16, 16, float> acc[2][3];
#pragma unroll
    for (int rt = 0; rt < 2; rt++)
#pragma unroll
        for (int g = 0; g < 3; g++)
            wmma::load_matrix_sync(acc[rt][g], &btile[g * 16], 48, wmma::mem_row_major);
    __syncthreads();

    for (int ch = 0; ch < 33; ch++) {
        float av[16];
        if (ch < 32) {
            const int kb = ch * 16;
            float4 a0 = *(const float4*)(Xr + kb);
            float4 a1 = *(const float4*)(Xr + kb + 4);
            float4 a2 = *(const float4*)(Xr + kb + 8);
            float4 a3 = *(const float4*)(Xr + kb + 12);
            av[0]=a0.x; av[1]=a0.y; av[2]=a0.z;  av[3]=a0.w;
            av[4]=a1.x; av[5]=a1.y; av[6]=a1.z;  av[7]=a1.w;
            av[8]=a2.x; av[9]=a2.y; av[10]=a2.z; av[11]=a2.w;
            av[12]=a3.x; av[13]=a3.y; av[14]=a3.z; av[15]=a3.w;
        } else {
            float4 m0v = *(const float4*)&g_MA[(size_t)m * A_DIM];
            float4 m1v = *(const float4*)&g_MA[(size_t)m * A_DIM + 4];
            av[0]=m0v.x; av[1]=m0v.y; av[2]=m0v.z; av[3]=m0v.w;
            av[4]=m1v.x; av[5]=m1v.y; av[6]=m1v.z; av[7]=m1v.w;
#pragma unroll
            for (int u = 8; u < 16; u++) av[u] = 0.0f;
        }
        store_split16(&Ahi[tid * SP], &Alo[tid * SP], av);

        if (tid < 192) {
            const bool pad = (ch == 32) && (segW >= 8);
            const size_t off = (size_t)wrow * K_IN + ch * 16 + segW;
            uint2 hv = pad ? make_uint2(0, 0) : *(const uint2*)(g_Wih_hi + off);
            uint2 lv = pad ? make_uint2(0, 0) : *(const uint2*)(g_Wih_lo + off);
            *(uint2*)&Whi[sW * SP + segW] = hv;
            *(uint2*)&Wlo[sW * SP + segW] = lv;
        }
        __syncthreads();

#pragma unroll
        for (int rt = 0; rt < 2; rt++) {
            wmma::fragment<wmma::matrix_a, 16, 16, 16, __nv_bfloat16, wmma::row_major> ahiF, aloF;
            wmma::load_matrix_sync(ahiF, &Ahi[(w * 32 + rt * 16) * SP], SP);
            wmma::load_matrix_sync(aloF, &Alo[(w * 32 + rt * 16) * SP], SP);
#pragma unroll
            for (int g = 0; g < 3; g++) {
                wmma::fragment<wmma::matrix_b, 16, 16, 16, __nv_bfloat16, wmma::col_major> bhiF, bloF;
                wmma::load_matrix_sync(bhiF, &Whi[(g * 16) * SP], SP);
                wmma::load_matrix_sync(bloF, &Wlo[(g * 16) * SP], SP);
                wmma::mma_sync(acc[rt][g], ahiF, bhiF, acc[rt][g]);
                wmma::mma_sync(acc[rt][g], ahiF, bloF, acc[rt][g]);
                wmma::mma_sync(acc[rt][g], aloF, bhiF, acc[rt][g]);
            }
        }
        __syncthreads();
    }

#pragma unroll
    for (int rt = 0; rt < 2; rt++)
#pragma unroll
        for (int g = 0; g < 3; g++) {
            int row0 = m0 + w * 32 + rt * 16;
            int col0 = g * H_DIM + j0;
            wmma::store_matrix_sync(g_GI + (size_t)row0 * G3 + col0, acc[rt][g], G3,
                                    wmma::mem_row_major);
        }
}

// ---------------------------------------------------------------------------
// Fused step kernel: bf16x3 wmma + fp32 epilogue. Double-buffered staging
// (1 sync/chunk), packed uint4 STS, vectorized epilogue.
// 128 CTAs x 256 threads. cta -> (gru, 16-col j-slice, 128-row half).
// Dynamic smem: 2 x (A 128x40 + W 48x40) bf16 hi/lo = 56,320 B; C overlays.
// ---------------------------------------------------------------------------
#define SP2 40
#define WSP 56
#define A_OFF_LO 5120            // bf16 units
#define W_OFF_HI 10240
#define W_OFF_LO 12160
#define BUF_STRIDE 14080         // bf16 units per buffer
#define STEP_DYN_SMEM (2 * BUF_STRIDE * 2)   // bytes = 56320

__device__ __forceinline__ void load_a16(const float* __restrict__ hrow,
                                         const float* __restrict__ grw,
                                         int kb, bool isp, float mr, float omr,
                                         float av[16]) {
    float4 h0 = *(const float4*)(hrow + kb);
    float4 h1 = *(const float4*)(hrow + kb + 4);
    float4 h2 = *(const float4*)(hrow + kb + 8);
    float4 h3 = *(const float4*)(hrow + kb + 12);
    av[0]=h0.x; av[1]=h0.y; av[2]=h0.z;  av[3]=h0.w;
    av[4]=h1.x; av[5]=h1.y; av[6]=h1.z;  av[7]=h1.w;
    av[8]=h2.x; av[9]=h2.y; av[10]=h2.z; av[11]=h2.w;
    av[12]=h3.x; av[13]=h3.y; av[14]=h3.z; av[15]=h3.w;
    if (isp) {
        float4 g0 = *(const float4*)(grw + kb);
        float4 g1 = *(const float4*)(grw + kb + 4);
        float4 g2 = *(const float4*)(grw + kb + 8);
        float4 g3 = *(const float4*)(grw + kb + 12);
        float gv[16] = {g0.x,g0.y,g0.z,g0.w, g1.x,g1.y,g1.z,g1.w,
                        g2.x,g2.y,g2.z,g2.w, g3.x,g3.y,g3.z,g3.w};
#pragma unroll
        for (int u = 0; u < 16; u++) av[u] = av[u] * mr + gv[u] * omr;
    } else {
#pragma unroll
        for (int u = 0; u < 16; u++) av[u] = av[u] * mr;
    }
}

__global__ void __launch_bounds__(256)
step_kernel(int t,
            const float* __restrict__ hx_prev, const float* __restrict__ hy_prev,
            const float* __restrict__ masks_t, const float* __restrict__ g_t,
            const float* __restrict__ b_hh, const float* __restrict__ b_hh_p,
            const float* __restrict__ w_ih_p, const float* __restrict__ b_ih_p,
            float* __restrict__ hx_out, float* __restrict__ hy_out) {
    extern __shared__ __align__(16) float dyn[];
    __shared__ float wp[48 * 8];
    __shared__ float bgs[48];
    __shared__ float bip[48];

    __nv_bfloat16* smb = (__nv_bfloat16*)dyn;

    const int cta = blockIdx.x;
    const bool isp = (cta >= 64);
    const int q = cta & 63;
    const int j0 = (q >> 1) * 16;
    const int mbase = (q & 1) * 128;

    const __nv_bfloat16* __restrict__ WhiG = isp ? g_Whp_hi : g_Whh_hi;
    const __nv_bfloat16* __restrict__ WloG = isp ? g_Whp_lo : g_Whh_lo;
    const float* __restrict__ bh = isp ? b_hh_p : b_hh;
    const float* __restrict__ hp = isp ? hy_prev : hx_prev;
    float* __restrict__ hout     = isp ? hy_out  : hx_out;

    const int tid = threadIdx.x;
    const int w = tid >> 5;
    const int lr  = tid >> 1;           // A row 0..127
    const int kh2 = (tid & 1) * 16;     // A k-half (0 or 16)
    const int kh  = (tid & 1) * 8;      // epilogue col-half
    const int sW  = tid >> 2;           // W s-row (valid tid<192)
    const int segW8 = (tid & 3) * 8;    // W k-segment (8 wide)

    const int grow = mbase + lr;
    const float mr = masks_t[grow];
    const float omr = 1.0f - mr;
    const float* __restrict__ hrow = hp  + (size_t)grow * H_DIM;
    const float* __restrict__ grw  = g_t + (size_t)grow * H_DIM;

    if (tid < 48) {
        const int gidx = (tid >> 4) * H_DIM + j0 + (tid & 15);
        bgs[tid] = bh[gidx];
        bip[tid] = b_ih_p[gidx];
    }
    if (tid < 96) {
        const int s = tid >> 1, hf = (tid & 1) * 4;
        const int gidx = (s >> 4) * H_DIM + j0 + (s & 15);
        *(float4*)&wp[s * 8 + hf] = *(const float4*)&w_ih_p[(size_t)gidx * A_DIM + hf];
    }

    const int wrow = (sW >> 4) * H_DIM + j0 + (sW & 15);
    const __nv_bfloat16* __restrict__ WhiR = WhiG + (size_t)wrow * H_DIM;
    const __nv_bfloat16* __restrict__ WloR = WloG + (size_t)wrow * H_DIM;

    wmma::fragment<wmma::accumulator, 16, 16, 16, float> acc[3];
#pragma unroll
    for (int g = 0; g < 3; g++) wmma::fill_fragment(acc[g], 0.0f);

    // stage chunk 0 into buffer 0
    {
        float av[16];
        load_a16(hrow, grw, kh2, isp, mr, omr, av);
        store_split16(smb + lr * SP2 + kh2, smb + A_OFF_LO + lr * SP2 + kh2, av);
        if (tid < 192) {
            *(uint4*)&smb[W_OFF_HI + sW * SP2 + segW8] = *(const uint4*)(WhiR + segW8);
            *(uint4*)&smb[W_OFF_LO + sW * SP2 + segW8] = *(const uint4*)(WloR + segW8);
        }
    }
    __syncthreads();

    for (int ch = 0; ch < 16; ch++) {
        const int cb = (ch & 1) * BUF_STRIDE;
        const int nb = ((ch + 1) & 1) * BUF_STRIDE;

        // prefetch next chunk into registers
        float av[16];
        uint4 whv, wlv;
        if (ch < 15) {
            load_a16(hrow, grw, (ch + 1) * 32 + kh2, isp, mr, omr, av);
            if (tid < 192) {
                whv = *(const uint4*)(WhiR + (ch + 1) * 32 + segW8);
                wlv = *(const uint4*)(WloR + (ch + 1) * 32 + segW8);
            }
        }

        // compute current buffer: warp w -> rows w*16..+15, 3 gate tiles, 2 k16
#pragma unroll
        for (int k8 = 0; k8 < 2; k8++) {
            wmma::fragment<wmma::matrix_a, 16, 16, 16, __nv_bfloat16, wmma::row_major> ahiF, aloF;
            wmma::load_matrix_sync(ahiF, &smb[cb + (w * 16) * SP2 + k8 * 16], SP2);
            wmma::load_matrix_sync(aloF, &smb[cb + A_OFF_LO + (w * 16) * SP2 + k8 * 16], SP2);
#pragma unroll
            for (int g = 0; g < 3; g++) {
                wmma::fragment<wmma::matrix_b, 16, 16, 16, __nv_bfloat16, wmma::col_major> bhiF, bloF;
                wmma::load_matrix_sync(bhiF, &smb[cb + W_OFF_HI + (g * 16) * SP2 + k8 * 16], SP2);
                wmma::load_matrix_sync(bloF, &smb[cb + W_OFF_LO + (g * 16) * SP2 + k8 * 16], SP2);
                wmma::mma_sync(acc[g], ahiF, bhiF, acc[g]);
                wmma::mma_sync(acc[g], ahiF, bloF, acc[g]);
                wmma::mma_sync(acc[g], aloF, bhiF, acc[g]);
            }
        }

        // store next chunk into the other buffer (read-safe since ch-1 synced)
        if (ch < 15) {
            store_split16(smb + nb + lr * SP2 + kh2,
                          smb + nb + A_OFF_LO + lr * SP2 + kh2, av);
            if (tid < 192) {
                *(uint4*)&smb[nb + W_OFF_HI + sW * SP2 + segW8] = whv;
                *(uint4*)&smb[nb + W_OFF_LO + sW * SP2 + segW8] = wlv;
            }
        }
        __syncthreads();
    }

    // ---- write C to smem (overlays buffers; all MMA reads complete) ----
    float* Csh = dyn;
#pragma unroll
    for (int g = 0; g < 3; g++)
        wmma::store_matrix_sync(&Csh[(w * 16) * WSP + g * 16], acc[g], WSP,
                                wmma::mem_row_major);
    __syncthreads();

    // ---- fused gate epilogue (vectorized): row lr, cols kh..kh+7 ----
    float cr[8], cz[8], cn[8];
    *(float4*)&cr[0] = *(const float4*)&Csh[lr * WSP + kh];
    *(float4*)&cr[4] = *(const float4*)&Csh[lr * WSP + kh + 4];
    *(float4*)&cz[0] = *(const float4*)&Csh[lr * WSP + 16 + kh];
    *(float4*)&cz[4] = *(const float4*)&Csh[lr * WSP + 16 + kh + 4];
    *(float4*)&cn[0] = *(const float4*)&Csh[lr * WSP + 32 + kh];
    *(float4*)&cn[4] = *(const float4*)&Csh[lr * WSP + 32 + kh + 4];

    const float* __restrict__ gi = g_GI + ((size_t)t * NB + grow) * G3 + j0;
    float gr_[8], gz_[8], gn_[8];
    if (!isp) {
        *(float4*)&gr_[0] = *(const float4*)(gi + kh);
        *(float4*)&gr_[4] = *(const float4*)(gi + kh + 4);
        *(float4*)&gz_[0] = *(const float4*)(gi + 512 + kh);
        *(float4*)&gz_[4] = *(const float4*)(gi + 512 + kh + 4);
        *(float4*)&gn_[0] = *(const float4*)(gi + 1024 + kh);
        *(float4*)&gn_[4] = *(const float4*)(gi + 1024 + kh + 4);
    } else {
        float ma8[8];
        float4 m0 = *(const float4*)&g_MA[((size_t)t * NB + grow) * A_DIM];
        float4 m1 = *(const float4*)&g_MA[((size_t)t * NB + grow) * A_DIM + 4];
        ma8[0]=m0.x; ma8[1]=m0.y; ma8[2]=m0.z; ma8[3]=m0.w;
        ma8[4]=m1.x; ma8[5]=m1.y; ma8[6]=m1.z; ma8[7]=m1.w;
#pragma unroll
        for (int u = 0; u < 8; u++) {
            const int jc = kh + u;
            float ir = bip[jc], iz = bip[16 + jc], in_ = bip[32 + jc];
#pragma unroll
            for (int a = 0; a < 8; a++) {
                ir  += ma8[a] * wp[jc * 8 + a];
                iz  += ma8[a] * wp[(16 + jc) * 8 + a];
                in_ += ma8[a] * wp[(32 + jc) * 8 + a];
            }
            gr_[u] = ir; gz_[u] = iz; gn_[u] = in_;
        }
    }

    float hv[8], hing[8];
    *(float4*)&hv[0] = *(const float4*)(hrow + j0 + kh);
    *(float4*)&hv[4] = *(const float4*)(hrow + j0 + kh + 4);
    if (isp) {
        float gg[8];
        *(float4*)&gg[0] = *(const float4*)(grw + j0 + kh);
        *(float4*)&gg[4] = *(const float4*)(grw + j0 + kh + 4);
#pragma unroll
        for (int u = 0; u < 8; u++) hing[u] = hv[u] * mr + gg[u] * omr;
    } else {
#pragma unroll
        for (int u = 0; u < 8; u++) hing[u] = hv[u] * mr;
    }

    float outv[8];
#pragma unroll
    for (int u = 0; u < 8; u++) {
        const int jc = kh + u;
        float r  = sigmoidf_(gr_[u] + cr[u] + bgs[jc]);
        float z  = sigmoidf_(gz_[u] + cz[u] + bgs[16 + jc]);
        float nn = tanhf(gn_[u] + r * (cn[u] + bgs[32 + jc]));
        outv[u] = (1.0f - z) * nn + z * hing[u];
    }
    *(float4*)(hout + (size_t)grow * H_DIM + j0 + kh)     = *(const float4*)&outv[0];
    *(float4*)(hout + (size_t)grow * H_DIM + j0 + kh + 4) = *(const float4*)&outv[4];
}

// ---------------------------------------------------------------------------
// Launch
// ---------------------------------------------------------------------------
extern "C" void kernel_launch(void* const* d_in, const int* in_sizes, int n_in,
                              void* d_out, int out_size) {
    const float* x        = (const float*)d_in[0];
    const float* hxs      = (const float*)d_in[1];
    const float* hys      = (const float*)d_in[2];
    const float* gru_init = (const float*)d_in[3];
    const float* masks    = (const float*)d_in[4];
    const float* pa       = (const float*)d_in[5];
    const float* w_ih     = (const float*)d_in[6];
    const float* w_hh     = (const float*)d_in[7];
    const float* b_ih     = (const float*)d_in[8];
    const float* b_hh     = (const float*)d_in[9];
    const float* w_ih_p   = (const float*)d_in[10];
    const float* w_hh_p   = (const float*)d_in[11];
    const float* b_ih_p   = (const float*)d_in[12];
    const float* b_hh_p   = (const float*)d_in[13];

    float* out      = (float*)d_out;
    float* outs     = out;                                   // (TN, H)
    float* hxs_out  = outs + (size_t)TN * H_DIM;             // (N, H)
    float* outs_p   = hxs_out + (size_t)NB * H_DIM;          // (TN, H)
    float* hys_out  = outs_p + (size_t)TN * H_DIM;           // (N, H)

    // allow 56.3KB dynamic smem for the step kernel (idempotent, every call)
    cudaFuncSetAttribute(step_kernel, cudaFuncAttributeMaxDynamicSharedMemorySize,
                         STEP_DYN_SMEM);

    // 1) masked prev-action + weight pre-split
    ma_kernel<<<(TN * A_DIM + 255) / 256, 256>>>(pa, masks);
    split3_kernel<<<(G3 * K_IN / 8 + 255) / 256, 256>>>(w_ih, w_hh, w_hh_p);

    // 2) big input GEMM (bf16x3 wmma, bias fused): g_GI complete
    input_gemm_kernel<<<dim3(G3 / 48, TN / 256), 256>>>(x, b_ih);

    // 3) sequential scan, one fused kernel per step
    const float* hx_prev = hxs;
    const float* hy_prev = hys;
    for (int t = 0; t < T_STEPS; t++) {
        const float* masks_t = masks + (size_t)t * NB;
        const float* g_t     = gru_init + (size_t)t * NB * H_DIM;
        float* hx_out = outs   + (size_t)t * NB * H_DIM;
        float* hy_out = outs_p + (size_t)t * NB * H_DIM;

        step_kernel<<<128, 256, STEP_DYN_SMEM>>>(t, hx_prev, hy_prev, masks_t, g_t,
                                                 b_hh, b_hh_p, w_ih_p, b_ih_p,
                                                 hx_out, hy_out);
        hx_prev = hx_out;
        hy_prev = hy_out;
    }

    // 4) final hidden states = last timestep outputs
    cudaMemcpyAsync(hxs_out, outs   + (size_t)(T_STEPS - 1) * NB * H_DIM,
                    (size_t)NB * H_DIM * sizeof(float), cudaMemcpyDeviceToDevice);
    cudaMemcpyAsync(hys_out, outs_p + (size_t)(T_STEPS - 1) * NB * H_DIM,
                    (size_t)NB * H_DIM * sizeof(float), cudaMemcpyDeviceToDevice);
}

// round 10
// speedup vs baseline: 2.9259x; 1.0884x over previous
#include <cuda_runtime.h>
#include <cuda_bf16.h>
#include <mma.h>
#include <math.h>
#include <stdint.h>

using namespace nvcuda;

#define T_STEPS 128
#define NB      256
#define E_DIM   512
#define A_DIM   8
#define H_DIM   512
#define G3      1536
#define TN      (T_STEPS * NB)
#define K_IN    (E_DIM + A_DIM)

// ---- scratch (device globals; no dynamic allocation allowed) ----
__device__ float g_GI[(size_t)TN * G3];   // input-side gates for gru (192 MiB)
__device__ float g_MA[TN * A_DIM];        // masked prev action

// pre-split bf16 weights (hi/lo)
__device__ __nv_bfloat16 g_Wih_hi[G3 * K_IN],  g_Wih_lo[G3 * K_IN];
__device__ __nv_bfloat16 g_Whh_hi[G3 * H_DIM], g_Whh_lo[G3 * H_DIM];
__device__ __nv_bfloat16 g_Whp_hi[G3 * H_DIM], g_Whp_lo[G3 * H_DIM];

__device__ __forceinline__ float sigmoidf_(float x) { return 1.0f / (1.0f + expf(-x)); }

__device__ __forceinline__ void split_bf16(float v, __nv_bfloat16& hi, __nv_bfloat16& lo) {
    hi = __float2bfloat16(v);
    lo = __float2bfloat16(v - __bfloat162float(hi));
}

// pack 16 floats -> 2x uint4 hi + 2x uint4 lo stores (16B each)
__device__ __forceinline__ void store_split16(__nv_bfloat16* hiDst, __nv_bfloat16* loDst,
                                              const float av[16]) {
    __nv_bfloat162 hp[8], lp[8];
#pragma unroll
    for (int u = 0; u < 8; u++) {
        __nv_bfloat16 h0, l0, h1, l1;
        split_bf16(av[2 * u],     h0, l0);
        split_bf16(av[2 * u + 1], h1, l1);
        hp[u] = __halves2bfloat162(h0, h1);
        lp[u] = __halves2bfloat162(l0, l1);
    }
    *(uint4*)(hiDst)     = *(const uint4*)&hp[0];
    *(uint4*)(hiDst + 8) = *(const uint4*)&hp[4];
    *(uint4*)(loDst)     = *(const uint4*)&lp[0];
    *(uint4*)(loDst + 8) = *(const uint4*)&lp[4];
}

// ---------------------------------------------------------------------------
// Prep: ma (proven)
// ---------------------------------------------------------------------------
__global__ void ma_kernel(const float* __restrict__ pa, const float* __restrict__ masks) {
    int i = blockIdx.x * blockDim.x + threadIdx.x;
    if (i < TN * A_DIM) g_MA[i] = pa[i] * masks[i >> 3];
}

// ---------------------------------------------------------------------------
// Prep: split all weights into bf16 hi/lo (proven)
// ---------------------------------------------------------------------------
__global__ void split3_kernel(const float* __restrict__ w_ih,
                              const float* __restrict__ w_hh,
                              const float* __restrict__ w_hh_p) {
    int i8 = (blockIdx.x * blockDim.x + threadIdx.x) * 8;
    if (i8 < G3 * K_IN) {
        float4 v0 = *(const float4*)(w_ih + i8);
        float4 v1 = *(const float4*)(w_ih + i8 + 4);
        float v[8] = {v0.x, v0.y, v0.z, v0.w, v1.x, v1.y, v1.z, v1.w};
        __nv_bfloat162 hp[4], lp[4];
#pragma unroll
        for (int u = 0; u < 4; u++) {
            __nv_bfloat16 h0, l0, h1, l1;
            split_bf16(v[2 * u], h0, l0);
            split_bf16(v[2 * u + 1], h1, l1);
            hp[u] = __halves2bfloat162(h0, h1);
            lp[u] = __halves2bfloat162(l0, l1);
        }
        *(uint4*)&g_Wih_hi[i8] = *(const uint4*)&hp[0];
        *(uint4*)&g_Wih_lo[i8] = *(const uint4*)&lp[0];
    }
    if (i8 < G3 * H_DIM) {
        {
            float4 v0 = *(const float4*)(w_hh + i8);
            float4 v1 = *(const float4*)(w_hh + i8 + 4);
            float v[8] = {v0.x, v0.y, v0.z, v0.w, v1.x, v1.y, v1.z, v1.w};
            __nv_bfloat162 hp[4], lp[4];
#pragma unroll
            for (int u = 0; u < 4; u++) {
                __nv_bfloat16 h0, l0, h1, l1;
                split_bf16(v[2 * u], h0, l0);
                split_bf16(v[2 * u + 1], h1, l1);
                hp[u] = __halves2bfloat162(h0, h1);
                lp[u] = __halves2bfloat162(l0, l1);
            }
            *(uint4*)&g_Whh_hi[i8] = *(const uint4*)&hp[0];
            *(uint4*)&g_Whh_lo[i8] = *(const uint4*)&lp[0];
        }
        {
            float4 v0 = *(const float4*)(w_hh_p + i8);
            float4 v1 = *(const float4*)(w_hh_p + i8 + 4);
            float v[8] = {v0.x, v0.y, v0.z, v0.w, v1.x, v1.y, v1.z, v1.w};
            __nv_bfloat162 hp[4], lp[4];
#pragma unroll
            for (int u = 0; u < 4; u++) {
                __nv_bfloat16 h0, l0, h1, l1;
                split_bf16(v[2 * u], h0, l0);
                split_bf16(v[2 * u + 1], h1, l1);
                hp[u] = __halves2bfloat162(h0, h1);
                lp[u] = __halves2bfloat162(l0, l1);
            }
            *(uint4*)&g_Whp_hi[i8] = *(const uint4*)&hp[0];
            *(uint4*)&g_Whp_lo[i8] = *(const uint4*)&lp[0];
        }
    }
}

// ---------------------------------------------------------------------------
// Input GEMM (bf16x3 wmma, proven round-9)
// ---------------------------------------------------------------------------
#define SP 24

__global__ void __launch_bounds__(256)
input_gemm_kernel(const float* __restrict__ X, const float* __restrict__ b_ih) {
    __shared__ __nv_bfloat16 Ahi[256 * SP], Alo[256 * SP];
    __shared__ __nv_bfloat16 Whi[48 * SP],  Wlo[48 * SP];
    __shared__ float btile[16 * 48];

    const int j0 = blockIdx.x * 16;
    const int m0 = blockIdx.y * 256;
    const int tid = threadIdx.x;
    const int w = tid >> 5;

    const int m = m0 + tid;
    const float* __restrict__ Xr = X + (size_t)m * E_DIM;
    const int sW = tid >> 2;
    const int segW = (tid & 3) * 4;
    const int wrow = (sW >> 4) * H_DIM + j0 + (sW & 15);

    for (int i = tid; i < 16 * 48; i += 256) {
        int c = i % 48;
        btile[i] = b_ih[(c >> 4) * H_DIM + j0 + (c & 15)];
    }
    __syncthreads();

    wmma::fragment<wmma::accumulator, 16, 16, 16, float> acc[2][3];
#pragma unroll
    for (int rt = 0; rt < 2; rt++)
#pragma unroll
        for (int g = 0; g < 3; g++)
            wmma::load_matrix_sync(acc[rt][g], &btile[g * 16], 48, wmma::mem_row_major);
    __syncthreads();

    for (int ch = 0; ch < 33; ch++) {
        float av[16];
        if (ch < 32) {
            const int kb = ch * 16;
            float4 a0 = *(const float4*)(Xr + kb);
            float4 a1 = *(const float4*)(Xr + kb + 4);
            float4 a2 = *(const float4*)(Xr + kb + 8);
            float4 a3 = *(const float4*)(Xr + kb + 12);
            av[0]=a0.x; av[1]=a0.y; av[2]=a0.z;  av[3]=a0.w;
            av[4]=a1.x; av[5]=a1.y; av[6]=a1.z;  av[7]=a1.w;
            av[8]=a2.x; av[9]=a2.y; av[10]=a2.z; av[11]=a2.w;
            av[12]=a3.x; av[13]=a3.y; av[14]=a3.z; av[15]=a3.w;
        } else {
            float4 m0v = *(const float4*)&g_MA[(size_t)m * A_DIM];
            float4 m1v = *(const float4*)&g_MA[(size_t)m * A_DIM + 4];
            av[0]=m0v.x; av[1]=m0v.y; av[2]=m0v.z; av[3]=m0v.w;
            av[4]=m1v.x; av[5]=m1v.y; av[6]=m1v.z; av[7]=m1v.w;
#pragma unroll
            for (int u = 8; u < 16; u++) av[u] = 0.0f;
        }
        store_split16(&Ahi[tid * SP], &Alo[tid * SP], av);

        if (tid < 192) {
            const bool pad = (ch == 32) && (segW >= 8);
            const size_t off = (size_t)wrow * K_IN + ch * 16 + segW;
            uint2 hv = pad ? make_uint2(0, 0) : *(const uint2*)(g_Wih_hi + off);
            uint2 lv = pad ? make_uint2(0, 0) : *(const uint2*)(g_Wih_lo + off);
            *(uint2*)&Whi[sW * SP + segW] = hv;
            *(uint2*)&Wlo[sW * SP + segW] = lv;
        }
        __syncthreads();

#pragma unroll
        for (int rt = 0; rt < 2; rt++) {
            wmma::fragment<wmma::matrix_a, 16, 16, 16, __nv_bfloat16, wmma::row_major> ahiF, aloF;
            wmma::load_matrix_sync(ahiF, &Ahi[(w * 32 + rt * 16) * SP], SP);
            wmma::load_matrix_sync(aloF, &Alo[(w * 32 + rt * 16) * SP], SP);
#pragma unroll
            for (int g = 0; g < 3; g++) {
                wmma::fragment<wmma::matrix_b, 16, 16, 16, __nv_bfloat16, wmma::col_major> bhiF, bloF;
                wmma::load_matrix_sync(bhiF, &Whi[(g * 16) * SP], SP);
                wmma::load_matrix_sync(bloF, &Wlo[(g * 16) * SP], SP);
                wmma::mma_sync(acc[rt][g], ahiF, bhiF, acc[rt][g]);
                wmma::mma_sync(acc[rt][g], ahiF, bloF, acc[rt][g]);
                wmma::mma_sync(acc[rt][g], aloF, bhiF, acc[rt][g]);
            }
        }
        __syncthreads();
    }

#pragma unroll
    for (int rt = 0; rt < 2; rt++)
#pragma unroll
        for (int g = 0; g < 3; g++) {
            int row0 = m0 + w * 32 + rt * 16;
            int col0 = g * H_DIM + j0;
            wmma::store_matrix_sync(g_GI + (size_t)row0 * G3 + col0, acc[rt][g], G3,
                                    wmma::mem_row_major);
        }
}

// ---------------------------------------------------------------------------
// Fused step kernel: bf16x3 wmma, SPLIT-K across 2 warp-groups (16 warps).
// Group g computes K in [g*256, (g+1)*256) over 8 double-buffered chunks of 32;
// partial C tiles summed in the 512-thread epilogue.
// 128 CTAs x 512 threads. cta -> (gru, 16-col j-slice, 128-row half).
// ---------------------------------------------------------------------------
#define SP2 40
#define WSP 56
#define A_OFF_LO 5120            // bf16 units within a buffer
#define W_OFF_HI 10240
#define W_OFF_LO 12160
#define BUF_STRIDE 14080         // bf16 units per (group,buf)
#define STEP_DYN_SMEM (4 * BUF_STRIDE * 2)   // bytes = 112,640

__device__ __forceinline__ void load_a16(const float* __restrict__ hrow,
                                         const float* __restrict__ grw,
                                         int kb, bool isp, float mr, float omr,
                                         float av[16]) {
    float4 h0 = *(const float4*)(hrow + kb);
    float4 h1 = *(const float4*)(hrow + kb + 4);
    float4 h2 = *(const float4*)(hrow + kb + 8);
    float4 h3 = *(const float4*)(hrow + kb + 12);
    av[0]=h0.x; av[1]=h0.y; av[2]=h0.z;  av[3]=h0.w;
    av[4]=h1.x; av[5]=h1.y; av[6]=h1.z;  av[7]=h1.w;
    av[8]=h2.x; av[9]=h2.y; av[10]=h2.z; av[11]=h2.w;
    av[12]=h3.x; av[13]=h3.y; av[14]=h3.z; av[15]=h3.w;
    if (isp) {
        float4 g0 = *(const float4*)(grw + kb);
        float4 g1 = *(const float4*)(grw + kb + 4);
        float4 g2 = *(const float4*)(grw + kb + 8);
        float4 g3 = *(const float4*)(grw + kb + 12);
        float gv[16] = {g0.x,g0.y,g0.z,g0.w, g1.x,g1.y,g1.z,g1.w,
                        g2.x,g2.y,g2.z,g2.w, g3.x,g3.y,g3.z,g3.w};
#pragma unroll
        for (int u = 0; u < 16; u++) av[u] = av[u] * mr + gv[u] * omr;
    } else {
#pragma unroll
        for (int u = 0; u < 16; u++) av[u] = av[u] * mr;
    }
}

__global__ void __launch_bounds__(512)
step_kernel(int t,
            const float* __restrict__ hx_prev, const float* __restrict__ hy_prev,
            const float* __restrict__ masks_t, const float* __restrict__ g_t,
            const float* __restrict__ b_hh, const float* __restrict__ b_hh_p,
            const float* __restrict__ w_ih_p, const float* __restrict__ b_ih_p,
            float* __restrict__ hx_out, float* __restrict__ hy_out) {
    extern __shared__ __align__(16) float dyn[];
    __shared__ float wp[48 * 8];
    __shared__ float bgs[48];
    __shared__ float bip[48];

    __nv_bfloat16* smb = (__nv_bfloat16*)dyn;

    const int cta = blockIdx.x;
    const bool isp = (cta >= 64);
    const int q = cta & 63;
    const int j0 = (q >> 1) * 16;
    const int mbase = (q & 1) * 128;

    const __nv_bfloat16* __restrict__ WhiG = isp ? g_Whp_hi : g_Whh_hi;
    const __nv_bfloat16* __restrict__ WloG = isp ? g_Whp_lo : g_Whh_lo;
    const float* __restrict__ bh = isp ? b_hh_p : b_hh;
    const float* __restrict__ hp = isp ? hy_prev : hx_prev;
    float* __restrict__ hout     = isp ? hy_out  : hx_out;

    const int tid = threadIdx.x;
    const int grp  = tid >> 8;          // K-group 0/1
    const int gtid = tid & 255;         // tid within group
    const int wg   = (tid >> 5) & 7;    // warp within group
    const int kg0  = grp * 256;         // K base for this group

    // staging roles within group (round-9 proven index math)
    const int lr  = gtid >> 1;          // A row 0..127
    const int kh2 = (gtid & 1) * 16;    // A k-half (0 or 16)
    const int sW  = gtid >> 2;          // W s-row (valid gtid<192)
    const int segW8 = (gtid & 3) * 8;   // W k-segment (8 wide)

    const int grow = mbase + lr;
    const float mr = masks_t[grow];
    const float omr = 1.0f - mr;
    const float* __restrict__ hrow = hp  + (size_t)grow * H_DIM + kg0;
    const float* __restrict__ grw  = g_t + (size_t)grow * H_DIM + kg0;

    if (tid < 48) {
        const int gidx = (tid >> 4) * H_DIM + j0 + (tid & 15);
        bgs[tid] = bh[gidx];
        bip[tid] = b_ih_p[gidx];
    }
    if (tid < 96) {
        const int s = tid >> 1, hf = (tid & 1) * 4;
        const int gidx = (s >> 4) * H_DIM + j0 + (s & 15);
        *(float4*)&wp[s * 8 + hf] = *(const float4*)&w_ih_p[(size_t)gidx * A_DIM + hf];
    }

    const int wrow = (sW >> 4) * H_DIM + j0 + (sW & 15);
    const __nv_bfloat16* __restrict__ WhiR = WhiG + (size_t)wrow * H_DIM + kg0;
    const __nv_bfloat16* __restrict__ WloR = WloG + (size_t)wrow * H_DIM + kg0;

    wmma::fragment<wmma::accumulator, 16, 16, 16, float> acc[3];
#pragma unroll
    for (int g = 0; g < 3; g++) wmma::fill_fragment(acc[g], 0.0f);

    // stage chunk 0 into this group's buffer 0
    {
        float av[16];
        load_a16(hrow, grw, kh2, isp, mr, omr, av);
        const int b0 = grp * 2 * BUF_STRIDE;
        store_split16(smb + b0 + lr * SP2 + kh2,
                      smb + b0 + A_OFF_LO + lr * SP2 + kh2, av);
        if (gtid < 192) {
            *(uint4*)&smb[b0 + W_OFF_HI + sW * SP2 + segW8] = *(const uint4*)(WhiR + segW8);
            *(uint4*)&smb[b0 + W_OFF_LO + sW * SP2 + segW8] = *(const uint4*)(WloR + segW8);
        }
    }
    __syncthreads();

    for (int ch = 0; ch < 8; ch++) {
        const int cb = (grp * 2 + (ch & 1)) * BUF_STRIDE;
        const int nb = (grp * 2 + ((ch + 1) & 1)) * BUF_STRIDE;

        // prefetch next chunk into registers
        float av[16];
        uint4 whv, wlv;
        if (ch < 7) {
            load_a16(hrow, grw, (ch + 1) * 32 + kh2, isp, mr, omr, av);
            if (gtid < 192) {
                whv = *(const uint4*)(WhiR + (ch + 1) * 32 + segW8);
                wlv = *(const uint4*)(WloR + (ch + 1) * 32 + segW8);
            }
        }

        // compute current buffer: warp wg -> rows wg*16..+15, 3 gate tiles, 2 k16
#pragma unroll
        for (int k8 = 0; k8 < 2; k8++) {
            wmma::fragment<wmma::matrix_a, 16, 16, 16, __nv_bfloat16, wmma::row_major> ahiF, aloF;
            wmma::load_matrix_sync(ahiF, &smb[cb + (wg * 16) * SP2 + k8 * 16], SP2);
            wmma::load_matrix_sync(aloF, &smb[cb + A_OFF_LO + (wg * 16) * SP2 + k8 * 16], SP2);
#pragma unroll
            for (int g = 0; g < 3; g++) {
                wmma::fragment<wmma::matrix_b, 16, 16, 16, __nv_bfloat16, wmma::col_major> bhiF, bloF;
                wmma::load_matrix_sync(bhiF, &smb[cb + W_OFF_HI + (g * 16) * SP2 + k8 * 16], SP2);
                wmma::load_matrix_sync(bloF, &smb[cb + W_OFF_LO + (g * 16) * SP2 + k8 * 16], SP2);
                wmma::mma_sync(acc[g], ahiF, bhiF, acc[g]);
                wmma::mma_sync(acc[g], ahiF, bloF, acc[g]);
                wmma::mma_sync(acc[g], aloF, bhiF, acc[g]);
            }
        }

        // store next chunk into the other buffer
        if (ch < 7) {
            store_split16(smb + nb + lr * SP2 + kh2,
                          smb + nb + A_OFF_LO + lr * SP2 + kh2, av);
            if (gtid < 192) {
                *(uint4*)&smb[nb + W_OFF_HI + sW * SP2 + segW8] = whv;
                *(uint4*)&smb[nb + W_OFF_LO + sW * SP2 + segW8] = wlv;
            }
        }
        __syncthreads();
    }

    // ---- write partial C tiles to smem (two disjoint regions) ----
    float* Csh = dyn + grp * 128 * WSP;   // group g -> its own 128xWSP tile
#pragma unroll
    for (int g = 0; g < 3; g++)
        wmma::store_matrix_sync(&Csh[(wg * 16) * WSP + g * 16], acc[g], WSP,
                                wmma::mem_row_major);
    __syncthreads();

    // ---- fused gate epilogue: 512 threads, row = tid>>2, 4 cols each ----
    const int er  = tid >> 2;           // epilogue row 0..127
    const int cq  = (tid & 3) * 4;      // col base within 16-slice
    const int egrow = mbase + er;
    const float emr = masks_t[egrow];
    const float eomr = 1.0f - emr;
    const float* __restrict__ C0 = dyn + er * WSP;
    const float* __restrict__ C1 = dyn + 128 * WSP + er * WSP;

    float cr[4], cz[4], cn[4];
#pragma unroll
    for (int u = 0; u < 4; u++) {
        cr[u] = C0[cq + u]      + C1[cq + u];
        cz[u] = C0[16 + cq + u] + C1[16 + cq + u];
        cn[u] = C0[32 + cq + u] + C1[32 + cq + u];
    }

    const float* __restrict__ gi = g_GI + ((size_t)t * NB + egrow) * G3 + j0;
    float gr_[4], gz_[4], gn_[4];
    if (!isp) {
        *(float4*)&gr_[0] = *(const float4*)(gi + cq);
        *(float4*)&gz_[0] = *(const float4*)(gi + 512 + cq);
        *(float4*)&gn_[0] = *(const float4*)(gi + 1024 + cq);
    } else {
        float ma8[8];
        float4 m0 = *(const float4*)&g_MA[((size_t)t * NB + egrow) * A_DIM];
        float4 m1 = *(const float4*)&g_MA[((size_t)t * NB + egrow) * A_DIM + 4];
        ma8[0]=m0.x; ma8[1]=m0.y; ma8[2]=m0.z; ma8[3]=m0.w;
        ma8[4]=m1.x; ma8[5]=m1.y; ma8[6]=m1.z; ma8[7]=m1.w;
#pragma unroll
        for (int u = 0; u < 4; u++) {
            const int jc = cq + u;
            float ir = bip[jc], iz = bip[16 + jc], in_ = bip[32 + jc];
#pragma unroll
            for (int a = 0; a < 8; a++) {
                ir  += ma8[a] * wp[jc * 8 + a];
                iz  += ma8[a] * wp[(16 + jc) * 8 + a];
                in_ += ma8[a] * wp[(32 + jc) * 8 + a];
            }
            gr_[u] = ir; gz_[u] = iz; gn_[u] = in_;
        }
    }

    const float* __restrict__ ehrow = hp + (size_t)egrow * H_DIM;
    float hv[4], hing[4];
    *(float4*)&hv[0] = *(const float4*)(ehrow + j0 + cq);
    if (isp) {
        float gg[4];
        *(float4*)&gg[0] = *(const float4*)(g_t + (size_t)egrow * H_DIM + j0 + cq);
#pragma unroll
        for (int u = 0; u < 4; u++) hing[u] = hv[u] * emr + gg[u] * eomr;
    } else {
#pragma unroll
        for (int u = 0; u < 4; u++) hing[u] = hv[u] * emr;
    }

    float outv[4];
#pragma unroll
    for (int u = 0; u < 4; u++) {
        const int jc = cq + u;
        float r  = sigmoidf_(gr_[u] + cr[u] + bgs[jc]);
        float z  = sigmoidf_(gz_[u] + cz[u] + bgs[16 + jc]);
        float nn = tanhf(gn_[u] + r * (cn[u] + bgs[32 + jc]));
        outv[u] = (1.0f - z) * nn + z * hing[u];
    }
    *(float4*)(hout + (size_t)egrow * H_DIM + j0 + cq) = *(const float4*)&outv[0];
}

// ---------------------------------------------------------------------------
// Launch
// ---------------------------------------------------------------------------
extern "C" void kernel_launch(void* const* d_in, const int* in_sizes, int n_in,
                              void* d_out, int out_size) {
    const float* x        = (const float*)d_in[0];
    const float* hxs      = (const float*)d_in[1];
    const float* hys      = (const float*)d_in[2];
    const float* gru_init = (const float*)d_in[3];
    const float* masks    = (const float*)d_in[4];
    const float* pa       = (const float*)d_in[5];
    const float* w_ih     = (const float*)d_in[6];
    const float* w_hh     = (const float*)d_in[7];
    const float* b_ih     = (const float*)d_in[8];
    const float* b_hh     = (const float*)d_in[9];
    const float* w_ih_p   = (const float*)d_in[10];
    const float* w_hh_p   = (const float*)d_in[11];
    const float* b_ih_p   = (const float*)d_in[12];
    const float* b_hh_p   = (const float*)d_in[13];

    float* out      = (float*)d_out;
    float* outs     = out;                                   // (TN, H)
    float* hxs_out  = outs + (size_t)TN * H_DIM;             // (N, H)
    float* outs_p   = hxs_out + (size_t)NB * H_DIM;          // (TN, H)
    float* hys_out  = outs_p + (size_t)TN * H_DIM;           // (N, H)

    // allow 112.6KB dynamic smem (idempotent, every call)
    cudaFuncSetAttribute(step_kernel, cudaFuncAttributeMaxDynamicSharedMemorySize,
                         STEP_DYN_SMEM);

    // 1) masked prev-action + weight pre-split
    ma_kernel<<<(TN * A_DIM + 255) / 256, 256>>>(pa, masks);
    split3_kernel<<<(G3 * K_IN / 8 + 255) / 256, 256>>>(w_ih, w_hh, w_hh_p);

    // 2) big input GEMM (bf16x3 wmma, bias fused): g_GI complete
    input_gemm_kernel<<<dim3(G3 / 48, TN / 256), 256>>>(x, b_ih);

    // 3) sequential scan, one fused kernel per step
    const float* hx_prev = hxs;
    const float* hy_prev = hys;
    for (int t = 0; t < T_STEPS; t++) {
        const float* masks_t = masks + (size_t)t * NB;
        const float* g_t     = gru_init + (size_t)t * NB * H_DIM;
        float* hx_out = outs   + (size_t)t * NB * H_DIM;
        float* hy_out = outs_p + (size_t)t * NB * H_DIM;

        step_kernel<<<128, 512, STEP_DYN_SMEM>>>(t, hx_prev, hy_prev, masks_t, g_t,
                                                 b_hh, b_hh_p, w_ih_p, b_ih_p,
                                                 hx_out, hy_out);
        hx_prev = hx_out;
        hy_prev = hy_out;
    }

    // 4) final hidden states = last timestep outputs
    cudaMemcpyAsync(hxs_out, outs   + (size_t)(T_STEPS - 1) * NB * H_DIM,
                    (size_t)NB * H_DIM * sizeof(float), cudaMemcpyDeviceToDevice);
    cudaMemcpyAsync(hys_out, outs_p + (size_t)(T_STEPS - 1) * NB * H_DIM,
                    (size_t)NB * H_DIM * sizeof(float), cudaMemcpyDeviceToDevice);
}

// round 11
// speedup vs baseline: 3.0972x; 1.0586x over previous
#include <cuda_runtime.h>
#include <cuda_bf16.h>
#include <mma.h>
#include <math.h>
#include <stdint.h>

using namespace nvcuda;

#define T_STEPS 128
#define NB      256
#define E_DIM   512
#define A_DIM   8
#define H_DIM   512
#define G3      1536
#define TN      (T_STEPS * NB)
#define K_IN    (E_DIM + A_DIM)

// ---- scratch (device globals; no dynamic allocation allowed) ----
__device__ float g_GI[(size_t)TN * G3];   // input-side gates for gru (192 MiB)
__device__ float g_MA[TN * A_DIM];        // masked prev action
__device__ unsigned g_bar;                // global barrier counter

// pre-split bf16 weights (hi/lo)
__device__ __nv_bfloat16 g_Wih_hi[G3 * K_IN],  g_Wih_lo[G3 * K_IN];
__device__ __nv_bfloat16 g_Whh_hi[G3 * H_DIM], g_Whh_lo[G3 * H_DIM];
__device__ __nv_bfloat16 g_Whp_hi[G3 * H_DIM], g_Whp_lo[G3 * H_DIM];

__device__ __forceinline__ float sigmoidf_(float x) { return 1.0f / (1.0f + expf(-x)); }

__device__ __forceinline__ void split_bf16(float v, __nv_bfloat16& hi, __nv_bfloat16& lo) {
    hi = __float2bfloat16(v);
    lo = __float2bfloat16(v - __bfloat162float(hi));
}

__device__ __forceinline__ void store_split16(__nv_bfloat16* hiDst, __nv_bfloat16* loDst,
                                              const float av[16]) {
    __nv_bfloat162 hp[8], lp[8];
#pragma unroll
    for (int u = 0; u < 8; u++) {
        __nv_bfloat16 h0, l0, h1, l1;
        split_bf16(av[2 * u],     h0, l0);
        split_bf16(av[2 * u + 1], h1, l1);
        hp[u] = __halves2bfloat162(h0, h1);
        lp[u] = __halves2bfloat162(l0, l1);
    }
    *(uint4*)(hiDst)     = *(const uint4*)&hp[0];
    *(uint4*)(hiDst + 8) = *(const uint4*)&hp[4];
    *(uint4*)(loDst)     = *(const uint4*)&lp[0];
    *(uint4*)(loDst + 8) = *(const uint4*)&lp[4];
}

// ---------------------------------------------------------------------------
// Prep kernels (proven)
// ---------------------------------------------------------------------------
__global__ void ma_kernel(const float* __restrict__ pa, const float* __restrict__ masks) {
    int i = blockIdx.x * blockDim.x + threadIdx.x;
    if (i < TN * A_DIM) g_MA[i] = pa[i] * masks[i >> 3];
}

__global__ void bar_reset_kernel() { g_bar = 0u; }

__global__ void split3_kernel(const float* __restrict__ w_ih,
                              const float* __restrict__ w_hh,
                              const float* __restrict__ w_hh_p) {
    int i8 = (blockIdx.x * blockDim.x + threadIdx.x) * 8;
    if (i8 < G3 * K_IN) {
        float4 v0 = *(const float4*)(w_ih + i8);
        float4 v1 = *(const float4*)(w_ih + i8 + 4);
        float v[8] = {v0.x, v0.y, v0.z, v0.w, v1.x, v1.y, v1.z, v1.w};
        __nv_bfloat162 hp[4], lp[4];
#pragma unroll
        for (int u = 0; u < 4; u++) {
            __nv_bfloat16 h0, l0, h1, l1;
            split_bf16(v[2 * u], h0, l0);
            split_bf16(v[2 * u + 1], h1, l1);
            hp[u] = __halves2bfloat162(h0, h1);
            lp[u] = __halves2bfloat162(l0, l1);
        }
        *(uint4*)&g_Wih_hi[i8] = *(const uint4*)&hp[0];
        *(uint4*)&g_Wih_lo[i8] = *(const uint4*)&lp[0];
    }
    if (i8 < G3 * H_DIM) {
        {
            float4 v0 = *(const float4*)(w_hh + i8);
            float4 v1 = *(const float4*)(w_hh + i8 + 4);
            float v[8] = {v0.x, v0.y, v0.z, v0.w, v1.x, v1.y, v1.z, v1.w};
            __nv_bfloat162 hp[4], lp[4];
#pragma unroll
            for (int u = 0; u < 4; u++) {
                __nv_bfloat16 h0, l0, h1, l1;
                split_bf16(v[2 * u], h0, l0);
                split_bf16(v[2 * u + 1], h1, l1);
                hp[u] = __halves2bfloat162(h0, h1);
                lp[u] = __halves2bfloat162(l0, l1);
            }
            *(uint4*)&g_Whh_hi[i8] = *(const uint4*)&hp[0];
            *(uint4*)&g_Whh_lo[i8] = *(const uint4*)&lp[0];
        }
        {
            float4 v0 = *(const float4*)(w_hh_p + i8);
            float4 v1 = *(const float4*)(w_hh_p + i8 + 4);
            float v[8] = {v0.x, v0.y, v0.z, v0.w, v1.x, v1.y, v1.z, v1.w};
            __nv_bfloat162 hp[4], lp[4];
#pragma unroll
            for (int u = 0; u < 4; u++) {
                __nv_bfloat16 h0, l0, h1, l1;
                split_bf16(v[2 * u], h0, l0);
                split_bf16(v[2 * u + 1], h1, l1);
                hp[u] = __halves2bfloat162(h0, h1);
                lp[u] = __halves2bfloat162(l0, l1);
            }
            *(uint4*)&g_Whp_hi[i8] = *(const uint4*)&hp[0];
            *(uint4*)&g_Whp_lo[i8] = *(const uint4*)&lp[0];
        }
    }
}

// ---------------------------------------------------------------------------
// Input GEMM (bf16x3 wmma, proven round-9/10)
// ---------------------------------------------------------------------------
#define SP 24

__global__ void __launch_bounds__(256)
input_gemm_kernel(const float* __restrict__ X, const float* __restrict__ b_ih) {
    __shared__ __nv_bfloat16 Ahi[256 * SP], Alo[256 * SP];
    __shared__ __nv_bfloat16 Whi[48 * SP],  Wlo[48 * SP];
    __shared__ float btile[16 * 48];

    const int j0 = blockIdx.x * 16;
    const int m0 = blockIdx.y * 256;
    const int tid = threadIdx.x;
    const int w = tid >> 5;

    const int m = m0 + tid;
    const float* __restrict__ Xr = X + (size_t)m * E_DIM;
    const int sW = tid >> 2;
    const int segW = (tid & 3) * 4;
    const int wrow = (sW >> 4) * H_DIM + j0 + (sW & 15);

    for (int i = tid; i < 16 * 48; i += 256) {
        int c = i % 48;
        btile[i] = b_ih[(c >> 4) * H_DIM + j0 + (c & 15)];
    }
    __syncthreads();

    wmma::fragment<wmma::accumulator, 16, 16, 16, float> acc[2][3];
#pragma unroll
    for (int rt = 0; rt < 2; rt++)
#pragma unroll
        for (int g = 0; g < 3; g++)
            wmma::load_matrix_sync(acc[rt][g], &btile[g * 16], 48, wmma::mem_row_major);
    __syncthreads();

    for (int ch = 0; ch < 33; ch++) {
        float av[16];
        if (ch < 32) {
            const int kb = ch * 16;
            float4 a0 = *(const float4*)(Xr + kb);
            float4 a1 = *(const float4*)(Xr + kb + 4);
            float4 a2 = *(const float4*)(Xr + kb + 8);
            float4 a3 = *(const float4*)(Xr + kb + 12);
            av[0]=a0.x; av[1]=a0.y; av[2]=a0.z;  av[3]=a0.w;
            av[4]=a1.x; av[5]=a1.y; av[6]=a1.z;  av[7]=a1.w;
            av[8]=a2.x; av[9]=a2.y; av[10]=a2.z; av[11]=a2.w;
            av[12]=a3.x; av[13]=a3.y; av[14]=a3.z; av[15]=a3.w;
        } else {
            float4 m0v = *(const float4*)&g_MA[(size_t)m * A_DIM];
            float4 m1v = *(const float4*)&g_MA[(size_t)m * A_DIM + 4];
            av[0]=m0v.x; av[1]=m0v.y; av[2]=m0v.z; av[3]=m0v.w;
            av[4]=m1v.x; av[5]=m1v.y; av[6]=m1v.z; av[7]=m1v.w;
#pragma unroll
            for (int u = 8; u < 16; u++) av[u] = 0.0f;
        }
        store_split16(&Ahi[tid * SP], &Alo[tid * SP], av);

        if (tid < 192) {
            const bool pad = (ch == 32) && (segW >= 8);
            const size_t off = (size_t)wrow * K_IN + ch * 16 + segW;
            uint2 hv = pad ? make_uint2(0, 0) : *(const uint2*)(g_Wih_hi + off);
            uint2 lv = pad ? make_uint2(0, 0) : *(const uint2*)(g_Wih_lo + off);
            *(uint2*)&Whi[sW * SP + segW] = hv;
            *(uint2*)&Wlo[sW * SP + segW] = lv;
        }
        __syncthreads();

#pragma unroll
        for (int rt = 0; rt < 2; rt++) {
            wmma::fragment<wmma::matrix_a, 16, 16, 16, __nv_bfloat16, wmma::row_major> ahiF, aloF;
            wmma::load_matrix_sync(ahiF, &Ahi[(w * 32 + rt * 16) * SP], SP);
            wmma::load_matrix_sync(aloF, &Alo[(w * 32 + rt * 16) * SP], SP);
#pragma unroll
            for (int g = 0; g < 3; g++) {
                wmma::fragment<wmma::matrix_b, 16, 16, 16, __nv_bfloat16, wmma::col_major> bhiF, bloF;
                wmma::load_matrix_sync(bhiF, &Whi[(g * 16) * SP], SP);
                wmma::load_matrix_sync(bloF, &Wlo[(g * 16) * SP], SP);
                wmma::mma_sync(acc[rt][g], ahiF, bhiF, acc[rt][g]);
                wmma::mma_sync(acc[rt][g], ahiF, bloF, acc[rt][g]);
                wmma::mma_sync(acc[rt][g], aloF, bhiF, acc[rt][g]);
            }
        }
        __syncthreads();
    }

#pragma unroll
    for (int rt = 0; rt < 2; rt++)
#pragma unroll
        for (int g = 0; g < 3; g++) {
            int row0 = m0 + w * 32 + rt * 16;
            int col0 = g * H_DIM + j0;
            wmma::store_matrix_sync(g_GI + (size_t)row0 * G3 + col0, acc[rt][g], G3,
                                    wmma::mem_row_major);
        }
}

// ---------------------------------------------------------------------------
// Persistent scan kernel: all 128 steps, W resident in smem, global barrier.
// 128 CTAs x 512 threads (split-K over 2 groups, round-10 layout).
// Dynamic smem (bf16 units): Whi[48*520]@0, Wlo@24960, A 4x(hi 5120 + lo 5120)@49920.
// C (float) overlays A region at float offset 24960.
// ---------------------------------------------------------------------------
#define WPCH 520
#define SP2 40
#define WSP 56
#define W_LO_OFF 24960
#define AB_OFF   49920
#define ABUF     10240
#define SCAN_SMEM ((AB_OFF + 4 * ABUF) * 2)   // 181,760 bytes

__device__ __forceinline__ void load_a16_cg(const float* __restrict__ hrow,
                                            const float* __restrict__ grw,
                                            int kb, bool isp, float mr, float omr,
                                            float av[16]) {
    float4 h0 = __ldcg((const float4*)(hrow + kb));
    float4 h1 = __ldcg((const float4*)(hrow + kb + 4));
    float4 h2 = __ldcg((const float4*)(hrow + kb + 8));
    float4 h3 = __ldcg((const float4*)(hrow + kb + 12));
    av[0]=h0.x; av[1]=h0.y; av[2]=h0.z;  av[3]=h0.w;
    av[4]=h1.x; av[5]=h1.y; av[6]=h1.z;  av[7]=h1.w;
    av[8]=h2.x; av[9]=h2.y; av[10]=h2.z; av[11]=h2.w;
    av[12]=h3.x; av[13]=h3.y; av[14]=h3.z; av[15]=h3.w;
    if (isp) {
        float4 g0 = *(const float4*)(grw + kb);
        float4 g1 = *(const float4*)(grw + kb + 4);
        float4 g2 = *(const float4*)(grw + kb + 8);
        float4 g3 = *(const float4*)(grw + kb + 12);
        float gv[16] = {g0.x,g0.y,g0.z,g0.w, g1.x,g1.y,g1.z,g1.w,
                        g2.x,g2.y,g2.z,g2.w, g3.x,g3.y,g3.z,g3.w};
#pragma unroll
        for (int u = 0; u < 16; u++) av[u] = av[u] * mr + gv[u] * omr;
    } else {
#pragma unroll
        for (int u = 0; u < 16; u++) av[u] = av[u] * mr;
    }
}

__global__ void __launch_bounds__(512)
scan_kernel(const float* __restrict__ hxs, const float* __restrict__ hys,
            const float* __restrict__ gru_init, const float* __restrict__ masks,
            const float* __restrict__ b_hh, const float* __restrict__ b_hh_p,
            const float* __restrict__ w_ih_p, const float* __restrict__ b_ih_p,
            float* __restrict__ outs, float* __restrict__ outs_p) {
    extern __shared__ __align__(16) float dyn[];
    __shared__ float wp[48 * 8];
    __shared__ float bgs[48];
    __shared__ float bip[48];

    __nv_bfloat16* smb = (__nv_bfloat16*)dyn;
    float* Cf = dyn + W_LO_OFF;   // float offset 24960 = byte 99840 (A region start)

    const int cta = blockIdx.x;
    const bool isp = (cta >= 64);
    const int q = cta & 63;
    const int j0 = (q >> 1) * 16;
    const int mbase = (q & 1) * 128;

    const __nv_bfloat16* __restrict__ WhiG = isp ? g_Whp_hi : g_Whh_hi;
    const __nv_bfloat16* __restrict__ WloG = isp ? g_Whp_lo : g_Whh_lo;
    const float* __restrict__ bh = isp ? b_hh_p : b_hh;

    const int tid = threadIdx.x;
    const int grp  = tid >> 8;
    const int gtid = tid & 255;
    const int wg   = (tid >> 5) & 7;
    const int kg0  = grp * 256;

    const int lr  = gtid >> 1;
    const int kh2 = (gtid & 1) * 16;
    const int grow = mbase + lr;
    const int er  = tid >> 2;
    const int cq  = (tid & 3) * 4;
    const int egrow = mbase + er;

    // ---- one-time setup: stage W resident, biases, wp ----
    for (int i = tid; i < 48 * 64; i += 512) {
        const int r = i >> 6, s8 = (i & 63) * 8;
        const int wr = (r >> 4) * H_DIM + j0 + (r & 15);
        *(uint4*)&smb[r * WPCH + s8]            = *(const uint4*)&WhiG[(size_t)wr * H_DIM + s8];
        *(uint4*)&smb[W_LO_OFF + r * WPCH + s8] = *(const uint4*)&WloG[(size_t)wr * H_DIM + s8];
    }
    if (tid < 48) {
        const int gidx = (tid >> 4) * H_DIM + j0 + (tid & 15);
        bgs[tid] = bh[gidx];
        bip[tid] = b_ih_p[gidx];
    }
    if (tid < 96) {
        const int s = tid >> 1, hf = (tid & 1) * 4;
        const int gidx = (s >> 4) * H_DIM + j0 + (s & 15);
        *(float4*)&wp[s * 8 + hf] = *(const float4*)&w_ih_p[(size_t)gidx * A_DIM + hf];
    }
    __syncthreads();

    for (int t = 0; t < T_STEPS; t++) {
        const float* __restrict__ hxp = t ? outs   + (size_t)(t - 1) * NB * H_DIM : hxs;
        const float* __restrict__ hyp = t ? outs_p + (size_t)(t - 1) * NB * H_DIM : hys;
        const float* __restrict__ hp = isp ? hyp : hxp;
        float* __restrict__ hout = (isp ? outs_p : outs) + (size_t)t * NB * H_DIM;
        const float* __restrict__ masks_t = masks + t * NB;
        const float* __restrict__ g_t = gru_init + (size_t)t * NB * H_DIM;

        const float mr = masks_t[grow];
        const float omr = 1.0f - mr;
        const float* __restrict__ hrow = hp  + (size_t)grow * H_DIM + kg0;
        const float* __restrict__ grw  = g_t + (size_t)grow * H_DIM + kg0;

        // ---- epilogue prefetch (DRAM latency hidden behind chunk loop) ----
        const float emr = masks_t[egrow];
        float4 hv4 = __ldcg((const float4*)(hp + (size_t)egrow * H_DIM + j0 + cq));
        float4 gg4, gi_r4, gi_z4, gi_n4;
        float ma8[8];
        if (isp) {
            gg4 = *(const float4*)(g_t + (size_t)egrow * H_DIM + j0 + cq);
            float4 m0 = *(const float4*)&g_MA[((size_t)t * NB + egrow) * A_DIM];
            float4 m1 = *(const float4*)&g_MA[((size_t)t * NB + egrow) * A_DIM + 4];
            ma8[0]=m0.x; ma8[1]=m0.y; ma8[2]=m0.z; ma8[3]=m0.w;
            ma8[4]=m1.x; ma8[5]=m1.y; ma8[6]=m1.z; ma8[7]=m1.w;
        } else {
            const float* __restrict__ gi = g_GI + ((size_t)t * NB + egrow) * G3 + j0;
            gi_r4 = *(const float4*)(gi + cq);
            gi_z4 = *(const float4*)(gi + 512 + cq);
            gi_n4 = *(const float4*)(gi + 1024 + cq);
        }

        wmma::fragment<wmma::accumulator, 16, 16, 16, float> acc[3];
#pragma unroll
        for (int g = 0; g < 3; g++) wmma::fill_fragment(acc[g], 0.0f);

        // stage chunk 0 into this group's buffer 0
        {
            float av[16];
            load_a16_cg(hrow, grw, kh2, isp, mr, omr, av);
            const int b0 = AB_OFF + grp * 2 * ABUF;
            store_split16(smb + b0 + lr * SP2 + kh2,
                          smb + b0 + 5120 + lr * SP2 + kh2, av);
        }
        __syncthreads();

        for (int ch = 0; ch < 8; ch++) {
            const int cb = AB_OFF + (grp * 2 + (ch & 1)) * ABUF;
            const int nb = AB_OFF + (grp * 2 + ((ch + 1) & 1)) * ABUF;

            float av[16];
            if (ch < 7) load_a16_cg(hrow, grw, (ch + 1) * 32 + kh2, isp, mr, omr, av);

#pragma unroll
            for (int k8 = 0; k8 < 2; k8++) {
                const int kg = kg0 + ch * 32 + k8 * 16;
                wmma::fragment<wmma::matrix_a, 16, 16, 16, __nv_bfloat16, wmma::row_major> ahiF, aloF;
                wmma::load_matrix_sync(ahiF, &smb[cb + (wg * 16) * SP2 + k8 * 16], SP2);
                wmma::load_matrix_sync(aloF, &smb[cb + 5120 + (wg * 16) * SP2 + k8 * 16], SP2);
#pragma unroll
                for (int g = 0; g < 3; g++) {
                    wmma::fragment<wmma::matrix_b, 16, 16, 16, __nv_bfloat16, wmma::col_major> bhiF, bloF;
                    wmma::load_matrix_sync(bhiF, &smb[(g * 16) * WPCH + kg], WPCH);
                    wmma::load_matrix_sync(bloF, &smb[W_LO_OFF + (g * 16) * WPCH + kg], WPCH);
                    wmma::mma_sync(acc[g], ahiF, bhiF, acc[g]);
                    wmma::mma_sync(acc[g], ahiF, bloF, acc[g]);
                    wmma::mma_sync(acc[g], aloF, bhiF, acc[g]);
                }
            }

            if (ch < 7) {
                store_split16(smb + nb + lr * SP2 + kh2,
                              smb + nb + 5120 + lr * SP2 + kh2, av);
            }
            __syncthreads();
        }

        // ---- partial C tiles to smem (overlay A region) ----
        float* Csh = Cf + grp * 128 * WSP;
#pragma unroll
        for (int g = 0; g < 3; g++)
            wmma::store_matrix_sync(&Csh[(wg * 16) * WSP + g * 16], acc[g], WSP,
                                    wmma::mem_row_major);
        __syncthreads();

        // ---- fused gate epilogue: row er, 4 cols at cq ----
        const float* __restrict__ C0 = Cf + er * WSP;
        const float* __restrict__ C1 = Cf + 128 * WSP + er * WSP;
        float cr[4], cz[4], cn[4];
#pragma unroll
        for (int u = 0; u < 4; u++) {
            cr[u] = C0[cq + u]      + C1[cq + u];
            cz[u] = C0[16 + cq + u] + C1[16 + cq + u];
            cn[u] = C0[32 + cq + u] + C1[32 + cq + u];
        }

        float gr_[4], gz_[4], gn_[4];
        if (!isp) {
            *(float4*)&gr_[0] = gi_r4;
            *(float4*)&gz_[0] = gi_z4;
            *(float4*)&gn_[0] = gi_n4;
        } else {
#pragma unroll
            for (int u = 0; u < 4; u++) {
                const int jc = cq + u;
                float ir = bip[jc], iz = bip[16 + jc], in_ = bip[32 + jc];
#pragma unroll
                for (int a = 0; a < 8; a++) {
                    ir  += ma8[a] * wp[jc * 8 + a];
                    iz  += ma8[a] * wp[(16 + jc) * 8 + a];
                    in_ += ma8[a] * wp[(32 + jc) * 8 + a];
                }
                gr_[u] = ir; gz_[u] = iz; gn_[u] = in_;
            }
        }

        float hv[4], hing[4];
        *(float4*)&hv[0] = hv4;
        if (isp) {
            float gg[4];
            *(float4*)&gg[0] = gg4;
#pragma unroll
            for (int u = 0; u < 4; u++) hing[u] = hv[u] * emr + gg[u] * (1.0f - emr);
        } else {
#pragma unroll
            for (int u = 0; u < 4; u++) hing[u] = hv[u] * emr;
        }

        float outv[4];
#pragma unroll
        for (int u = 0; u < 4; u++) {
            const int jc = cq + u;
            float r  = sigmoidf_(gr_[u] + cr[u] + bgs[jc]);
            float z  = sigmoidf_(gz_[u] + cz[u] + bgs[16 + jc]);
            float nn = tanhf(gn_[u] + r * (cn[u] + bgs[32 + jc]));
            outv[u] = (1.0f - z) * nn + z * hing[u];
        }
        *(float4*)(hout + (size_t)egrow * H_DIM + j0 + cq) = *(const float4*)&outv[0];

        // ---- global barrier between steps ----
        __syncthreads();
        if (tid == 0) {
            __threadfence();
            atomicAdd(&g_bar, 1u);
            const unsigned tgt = (unsigned)(t + 1) * 128u;
            unsigned v;
            do {
                asm volatile("ld.acquire.gpu.u32 %0, [%1];" : "=r"(v) : "l"(&g_bar));
                if (v < tgt) __nanosleep(32);
            } while (v < tgt);
        }
        __syncthreads();
    }
}

// ---------------------------------------------------------------------------
// Launch
// ---------------------------------------------------------------------------
extern "C" void kernel_launch(void* const* d_in, const int* in_sizes, int n_in,
                              void* d_out, int out_size) {
    const float* x        = (const float*)d_in[0];
    const float* hxs      = (const float*)d_in[1];
    const float* hys      = (const float*)d_in[2];
    const float* gru_init = (const float*)d_in[3];
    const float* masks    = (const float*)d_in[4];
    const float* pa       = (const float*)d_in[5];
    const float* w_ih     = (const float*)d_in[6];
    const float* w_hh     = (const float*)d_in[7];
    const float* b_ih     = (const float*)d_in[8];
    const float* b_hh     = (const float*)d_in[9];
    const float* w_ih_p   = (const float*)d_in[10];
    const float* w_hh_p   = (const float*)d_in[11];
    const float* b_ih_p   = (const float*)d_in[12];
    const float* b_hh_p   = (const float*)d_in[13];

    float* out      = (float*)d_out;
    float* outs     = out;                                   // (TN, H)
    float* hxs_out  = outs + (size_t)TN * H_DIM;             // (N, H)
    float* outs_p   = hxs_out + (size_t)NB * H_DIM;          // (TN, H)
    float* hys_out  = outs_p + (size_t)TN * H_DIM;           // (N, H)

    cudaFuncSetAttribute(scan_kernel, cudaFuncAttributeMaxDynamicSharedMemorySize,
                         SCAN_SMEM);

    // 1) prep
    ma_kernel<<<(TN * A_DIM + 255) / 256, 256>>>(pa, masks);
    split3_kernel<<<(G3 * K_IN / 8 + 255) / 256, 256>>>(w_ih, w_hh, w_hh_p);
    bar_reset_kernel<<<1, 1>>>();

    // 2) input GEMM: g_GI complete
    input_gemm_kernel<<<dim3(G3 / 48, TN / 256), 256>>>(x, b_ih);

    // 3) persistent scan: all 128 steps in one launch
    scan_kernel<<<128, 512, SCAN_SMEM>>>(hxs, hys, gru_init, masks,
                                         b_hh, b_hh_p, w_ih_p, b_ih_p,
                                         outs, outs_p);

    // 4) final hidden states = last timestep outputs
    cudaMemcpyAsync(hxs_out, outs   + (size_t)(T_STEPS - 1) * NB * H_DIM,
                    (size_t)NB * H_DIM * sizeof(float), cudaMemcpyDeviceToDevice);
    cudaMemcpyAsync(hys_out, outs_p + (size_t)(T_STEPS - 1) * NB * H_DIM,
                    (size_t)NB * H_DIM * sizeof(float), cudaMemcpyDeviceToDevice);
}